// round 13
// baseline (speedup 1.0000x reference)
#include <cuda_runtime.h>
#include <cuda_fp16.h>
#include <cstdint>

// ---------------- problem constants ----------------
#define BB 4
#define NN 8192
#define CC 512
#define DD 128
#define HID 2048
#define MTOK 32768
#define EPS 1e-5f
#define SCALE 0.08838834764831845f   // 128^-0.5
#define CSPLIT 16

// ---------------- scratch ----------------
__device__ float  g_x1  [(size_t)MTOK * CC];          // fp32 residual
__device__ float  g_ctxp[(size_t)CSPLIT * 16 * DD * DD];
__device__ __half g_xh   [(size_t)MTOK * CC];         // LN1/LN2 out (fp16)
__device__ __half g_qkvh [(size_t)MTOK * 1536];       // fp16 q + LN'd k,v
__device__ __half g_attnh[(size_t)MTOK * CC];
__device__ __half g_mlphh[(size_t)MTOK * HID];
__device__ __half g_ctxh [(size_t)16 * DD * DD];
__device__ __half g_wh   [(size_t)3145728];           // all weights fp16

#define WH_QKV  0
#define WH_PROJ 786432
#define WH_MLP1 1048576
#define WH_MLP2 2097152

// ---------------- ptx helpers ----------------
__device__ __forceinline__ uint32_t smem_u32(const void* p) {
    uint32_t r;
    asm("{ .reg .u64 t; cvta.to.shared.u64 t, %1; cvt.u32.u64 %0, t; }" : "=r"(r) : "l"(p));
    return r;
}
__device__ __forceinline__ void mma_f16(float* d, const unsigned* a, const unsigned* b) {
    asm volatile(
        "mma.sync.aligned.m16n8k16.row.col.f32.f16.f16.f32 "
        "{%0,%1,%2,%3}, {%4,%5,%6,%7}, {%8,%9}, {%0,%1,%2,%3};"
        : "+f"(d[0]), "+f"(d[1]), "+f"(d[2]), "+f"(d[3])
        : "r"(a[0]), "r"(a[1]), "r"(a[2]), "r"(a[3]), "r"(b[0]), "r"(b[1]));
}
__device__ __forceinline__ void ldsm4(unsigned& r0, unsigned& r1, unsigned& r2, unsigned& r3, uint32_t a) {
    asm volatile("ldmatrix.sync.aligned.m8n8.x4.shared.b16 {%0,%1,%2,%3}, [%4];"
                 : "=r"(r0), "=r"(r1), "=r"(r2), "=r"(r3) : "r"(a));
}
__device__ __forceinline__ void ldsm4t(unsigned& r0, unsigned& r1, unsigned& r2, unsigned& r3, uint32_t a) {
    asm volatile("ldmatrix.sync.aligned.m8n8.x4.trans.shared.b16 {%0,%1,%2,%3}, [%4];"
                 : "=r"(r0), "=r"(r1), "=r"(r2), "=r"(r3) : "r"(a));
}
__device__ __forceinline__ void cpa16(uint32_t dst, const void* src) {
    asm volatile("cp.async.cg.shared.global [%0], [%1], 16;" :: "r"(dst), "l"(src));
}
#define CP_COMMIT() asm volatile("cp.async.commit_group;" ::: "memory")
#define CP_WAIT2()  asm volatile("cp.async.wait_group 2;" ::: "memory")

// ---------------- fused fp32 -> fp16 weight convert ----------------
__global__ void f2h_all(const float* __restrict__ a, const float* __restrict__ b,
                        const float* __restrict__ c, const float* __restrict__ d,
                        __half* __restrict__ out) {
    int i = (blockIdx.x * 256 + threadIdx.x) * 4;
    const float* src; int off;
    if (i < 786432)       { src = a; off = i; }
    else if (i < 1048576) { src = b; off = i - 786432; }
    else if (i < 2097152) { src = c; off = i - 1048576; }
    else                  { src = d; off = i - 2097152; }
    float4 v = *(const float4*)(src + off);
    __half2 h0 = __floats2half2_rn(v.x, v.y), h1 = __floats2half2_rn(v.z, v.w);
    uint2 u; u.x = *(unsigned*)&h0; u.y = *(unsigned*)&h1;
    *(uint2*)(out + i) = u;
}

// ---------------- LayerNorm over 512 (fp32 in, fp16 out) ----------------
__global__ void ln_rows512(const float* __restrict__ x, __half* __restrict__ y,
                           const float* __restrict__ w, const float* __restrict__ b) {
    int row = blockIdx.x;
    const float* xr = x + (size_t)row * CC;
    int t = threadIdx.x;
    float2 v = *(const float2*)(xr + 2 * t);
    float s = v.x + v.y, s2 = v.x * v.x + v.y * v.y;
#pragma unroll
    for (int o = 16; o > 0; o >>= 1) {
        s  += __shfl_xor_sync(0xffffffffu, s,  o);
        s2 += __shfl_xor_sync(0xffffffffu, s2, o);
    }
    __shared__ float sh[18];
    int wid = t >> 5, lane = t & 31;
    if (lane == 0) { sh[wid] = s; sh[wid + 8] = s2; }
    __syncthreads();
    if (t == 0) {
        float ts = 0.f, ts2 = 0.f;
#pragma unroll
        for (int i = 0; i < 8; i++) { ts += sh[i]; ts2 += sh[i + 8]; }
        float mu  = ts * (1.f / CC);
        float var = ts2 * (1.f / CC) - mu * mu;
        sh[16] = mu; sh[17] = rsqrtf(var + EPS);
    }
    __syncthreads();
    float mu = sh[16], inv = sh[17];
    float2 wv = *(const float2*)(w + 2 * t);
    float2 bv = *(const float2*)(b + 2 * t);
    __half2 o = __floats2half2_rn((v.x - mu) * inv * wv.x + bv.x,
                                  (v.y - mu) * inv * wv.y + bv.y);
    *(__half2*)(y + (size_t)row * CC + 2 * t) = o;
}

// ---------------- 512-thread GEMM mainloop ----------------
#define EPI_GELU 1
#define EPI_RES  2
#define HSM_BYTES ((4*128*40 + 4*32*264) * 2)

// ---------------- qkv GEMM, 512 threads, fused k/v LN epilogue --------------
__global__ __launch_bounds__(512, 1)
void qkv512(const __half* __restrict__ A, const __half* __restrict__ W,
            __half* __restrict__ Ch, const float* __restrict__ bias,
            const float* __restrict__ lnk_w, const float* __restrict__ lnk_b,
            const float* __restrict__ lnv_w, const float* __restrict__ lnv_b) {
    extern __shared__ __half hsm[];
    const int NTOT = 1536, K = 512;
    const int tid = threadIdx.x;
    const int m0 = blockIdx.y * 128, n0 = blockIdx.x * 256;
    const int lane = tid & 31, wid = tid >> 5;
    const int wm0 = (wid >> 3) * 64;
    const int wn0 = (wid & 7) * 32;
    const int g = lane >> 2, tq = lane & 3;
    const uint32_t sb = smem_u32(hsm);

    float acc[4][4][4];
#pragma unroll
    for (int i = 0; i < 4; i++)
#pragma unroll
        for (int j = 0; j < 4; j++)
#pragma unroll
            for (int c = 0; c < 4; c++) acc[i][j][c] = 0.f;

    const int am  = tid >> 2;
    const int akg = tid & 3;
    const int bk  = tid >> 5;
    const int bg  = tid & 31;
    const __half* aptr = A + (size_t)(m0 + am) * K + akg * 8;
    const __half* wptr = W + (size_t)bk * NTOT + n0 + bg * 8;
    const uint32_t adst = sb + (uint32_t)(am * 40 + akg * 8) * 2;
    const uint32_t bdst = sb + (uint32_t)(20480 + bk * 264 + bg * 8) * 2;

    const int NT = K / 32;
#pragma unroll 1
    for (int p = 0; p < 3; p++) {
        cpa16(adst + (uint32_t)(p * 5120) * 2, aptr + (size_t)p * 32);
        uint32_t bd = bdst + (uint32_t)(p * 8448) * 2;
        const __half* wp = wptr + (size_t)p * 32 * NTOT;
        cpa16(bd, wp);
        cpa16(bd + (uint32_t)(16 * 264) * 2, wp + (size_t)16 * NTOT);
        CP_COMMIT();
    }

    const int a_r = lane & 15;
    const int a_c = (lane >> 4) * 8;

#pragma unroll 1
    for (int t = 0; t < NT; t++) {
        CP_WAIT2();
        __syncthreads();
        if (t + 3 < NT) {
            const int sn = (t + 3) & 3;
            cpa16(adst + (uint32_t)(sn * 5120) * 2, aptr + (size_t)(t + 3) * 32);
            uint32_t bd = bdst + (uint32_t)(sn * 8448) * 2;
            const __half* wp = wptr + (size_t)(t + 3) * 32 * NTOT;
            cpa16(bd, wp);
            cpa16(bd + (uint32_t)(16 * 264) * 2, wp + (size_t)16 * NTOT);
        }
        CP_COMMIT();
        const int s = t & 3;
        const uint32_t as_ = sb + (uint32_t)(s * 5120) * 2;
        const uint32_t bs_ = sb + (uint32_t)(20480 + s * 8448) * 2;
#pragma unroll
        for (int ks = 0; ks < 2; ks++) {
            unsigned af[4][4], bf[4][2];
#pragma unroll
            for (int mt = 0; mt < 4; mt++)
                ldsm4(af[mt][0], af[mt][1], af[mt][2], af[mt][3],
                      as_ + (uint32_t)((wm0 + mt * 16 + a_r) * 40 + ks * 16 + a_c) * 2);
#pragma unroll
            for (int nq = 0; nq < 2; nq++)
                ldsm4t(bf[2 * nq][0], bf[2 * nq][1], bf[2 * nq + 1][0], bf[2 * nq + 1][1],
                       bs_ + (uint32_t)((ks * 16 + a_r) * 264 + wn0 + nq * 16 + a_c) * 2);
#pragma unroll
            for (int mt = 0; mt < 4; mt++)
#pragma unroll
                for (int nt = 0; nt < 4; nt++)
                    mma_f16(acc[mt][nt], af[mt], bf[nt]);
        }
    }

    // ---- bias ----
#pragma unroll
    for (int mt = 0; mt < 4; mt++)
#pragma unroll
        for (int nt = 0; nt < 4; nt++) {
            int cb = n0 + wn0 + nt * 8 + 2 * tq;
            float2 bv = *(const float2*)(bias + cb);
            acc[mt][nt][0] += bv.x; acc[mt][nt][1] += bv.y;
            acc[mt][nt][2] += bv.x; acc[mt][nt][3] += bv.y;
        }

    // ---- fused per-head LN for k (x∈{2,3}) / v (x∈{4,5}) ----
    if (blockIdx.x >= 2) {
        const float* lw = (blockIdx.x < 4) ? lnk_w : lnv_w;
        const float* lb = (blockIdx.x < 4) ? lnk_b : lnv_b;
        float* red = (float*)hsm;        // [2 heads][128 rows][4 nwarps][2] = 8KB
        const int head = (wid >> 2) & 1;
        const int j = wid & 3;
        float ps[4][2], ps2[4][2];
#pragma unroll
        for (int mt = 0; mt < 4; mt++)
#pragma unroll
            for (int h2 = 0; h2 < 2; h2++) {
                float s = 0.f, s2 = 0.f;
#pragma unroll
                for (int nt = 0; nt < 4; nt++) {
                    float a = acc[mt][nt][2 * h2], b = acc[mt][nt][2 * h2 + 1];
                    s += a + b; s2 += a * a + b * b;
                }
                ps[mt][h2] = s; ps2[mt][h2] = s2;
            }
#pragma unroll
        for (int off = 1; off < 4; off <<= 1)
#pragma unroll
            for (int mt = 0; mt < 4; mt++)
#pragma unroll
                for (int h2 = 0; h2 < 2; h2++) {
                    ps[mt][h2]  += __shfl_xor_sync(0xffffffffu, ps[mt][h2],  off);
                    ps2[mt][h2] += __shfl_xor_sync(0xffffffffu, ps2[mt][h2], off);
                }
        __syncthreads();
        if (tq == 0) {
#pragma unroll
            for (int mt = 0; mt < 4; mt++)
#pragma unroll
                for (int h2 = 0; h2 < 2; h2++) {
                    int row = wm0 + mt * 16 + g + 8 * h2;
                    int idx = ((head * 128 + row) * 4 + j) * 2;
                    red[idx] = ps[mt][h2]; red[idx + 1] = ps2[mt][h2];
                }
        }
        __syncthreads();
#pragma unroll
        for (int mt = 0; mt < 4; mt++) {
            float mu[2], inv[2];
#pragma unroll
            for (int h2 = 0; h2 < 2; h2++) {
                int row = wm0 + mt * 16 + g + 8 * h2;
                int i0 = (head * 128 + row) * 8;
                float s  = red[i0] + red[i0 + 2] + red[i0 + 4] + red[i0 + 6];
                float s2 = red[i0 + 1] + red[i0 + 3] + red[i0 + 5] + red[i0 + 7];
                float m = s * (1.f / 128);
                mu[h2] = m;
                inv[h2] = rsqrtf(s2 * (1.f / 128) - m * m + EPS);
            }
#pragma unroll
            for (int nt = 0; nt < 4; nt++) {
                int ch = j * 32 + nt * 8 + 2 * tq;
                float2 lwv = *(const float2*)(lw + ch);
                float2 lbv = *(const float2*)(lb + ch);
                acc[mt][nt][0] = (acc[mt][nt][0] - mu[0]) * inv[0] * lwv.x + lbv.x;
                acc[mt][nt][1] = (acc[mt][nt][1] - mu[0]) * inv[0] * lwv.y + lbv.y;
                acc[mt][nt][2] = (acc[mt][nt][2] - mu[1]) * inv[1] * lwv.x + lbv.x;
                acc[mt][nt][3] = (acc[mt][nt][3] - mu[1]) * inv[1] * lwv.y + lbv.y;
            }
        }
    }

    // ---- fp16 store ----
#pragma unroll
    for (int mt = 0; mt < 4; mt++) {
        int r0 = m0 + wm0 + mt * 16 + g;
#pragma unroll
        for (int nt = 0; nt < 4; nt++) {
            int cb = n0 + wn0 + nt * 8 + 2 * tq;
            __half2 h0 = __floats2half2_rn(acc[mt][nt][0], acc[mt][nt][1]);
            __half2 h1 = __floats2half2_rn(acc[mt][nt][2], acc[mt][nt][3]);
            *(__half2*)(Ch + (size_t)r0 * NTOT + cb) = h0;
            *(__half2*)(Ch + (size_t)(r0 + 8) * NTOT + cb) = h1;
        }
    }
}

// ---------------- 512-thread generic hgemm (128x256 tile) -------------------
template <int NTOT, int K, int WF32, int H16, int EPI>
__global__ __launch_bounds__(512, 1)
void hgemm512(const __half* __restrict__ A, const __half* __restrict__ W,
              float* __restrict__ C, __half* __restrict__ Ch,
              const float* __restrict__ bias, const float* __restrict__ res) {
    extern __shared__ __half hsm[];
    const int tid = threadIdx.x;
    const int m0 = blockIdx.y * 128, n0 = blockIdx.x * 256;
    const int lane = tid & 31, wid = tid >> 5;
    const int wm0 = (wid >> 3) * 64;
    const int wn0 = (wid & 7) * 32;
    const int g = lane >> 2, tq = lane & 3;
    const uint32_t sb = smem_u32(hsm);

    float acc[4][4][4];
#pragma unroll
    for (int i = 0; i < 4; i++)
#pragma unroll
        for (int j = 0; j < 4; j++)
#pragma unroll
            for (int c = 0; c < 4; c++) acc[i][j][c] = 0.f;

    const int am  = tid >> 2;
    const int akg = tid & 3;
    const int bk  = tid >> 5;
    const int bg  = tid & 31;
    const __half* aptr = A + (size_t)(m0 + am) * K + akg * 8;
    const __half* wptr = W + (size_t)bk * NTOT + n0 + bg * 8;
    const uint32_t adst = sb + (uint32_t)(am * 40 + akg * 8) * 2;
    const uint32_t bdst = sb + (uint32_t)(20480 + bk * 264 + bg * 8) * 2;

    const int NT = K / 32;
#pragma unroll 1
    for (int p = 0; p < 3; p++) {
        cpa16(adst + (uint32_t)(p * 5120) * 2, aptr + (size_t)p * 32);
        uint32_t bd = bdst + (uint32_t)(p * 8448) * 2;
        const __half* wp = wptr + (size_t)p * 32 * NTOT;
        cpa16(bd, wp);
        cpa16(bd + (uint32_t)(16 * 264) * 2, wp + (size_t)16 * NTOT);
        CP_COMMIT();
    }

    const int a_r = lane & 15;
    const int a_c = (lane >> 4) * 8;

#pragma unroll 1
    for (int t = 0; t < NT; t++) {
        CP_WAIT2();
        __syncthreads();
        if (t + 3 < NT) {
            const int sn = (t + 3) & 3;
            cpa16(adst + (uint32_t)(sn * 5120) * 2, aptr + (size_t)(t + 3) * 32);
            uint32_t bd = bdst + (uint32_t)(sn * 8448) * 2;
            const __half* wp = wptr + (size_t)(t + 3) * 32 * NTOT;
            cpa16(bd, wp);
            cpa16(bd + (uint32_t)(16 * 264) * 2, wp + (size_t)16 * NTOT);
        }
        CP_COMMIT();
        const int s = t & 3;
        const uint32_t as_ = sb + (uint32_t)(s * 5120) * 2;
        const uint32_t bs_ = sb + (uint32_t)(20480 + s * 8448) * 2;
#pragma unroll
        for (int ks = 0; ks < 2; ks++) {
            unsigned af[4][4], bf[4][2];
#pragma unroll
            for (int mt = 0; mt < 4; mt++)
                ldsm4(af[mt][0], af[mt][1], af[mt][2], af[mt][3],
                      as_ + (uint32_t)((wm0 + mt * 16 + a_r) * 40 + ks * 16 + a_c) * 2);
#pragma unroll
            for (int nq = 0; nq < 2; nq++)
                ldsm4t(bf[2 * nq][0], bf[2 * nq][1], bf[2 * nq + 1][0], bf[2 * nq + 1][1],
                       bs_ + (uint32_t)((ks * 16 + a_r) * 264 + wn0 + nq * 16 + a_c) * 2);
#pragma unroll
            for (int mt = 0; mt < 4; mt++)
#pragma unroll
                for (int nt = 0; nt < 4; nt++)
                    mma_f16(acc[mt][nt], af[mt], bf[nt]);
        }
    }

#pragma unroll
    for (int mt = 0; mt < 4; mt++) {
        int r0 = m0 + wm0 + mt * 16 + g;
#pragma unroll
        for (int nt = 0; nt < 4; nt++) {
            int cb = n0 + wn0 + nt * 8 + 2 * tq;
            float2 bv = *(const float2*)(bias + cb);
            float v0 = acc[mt][nt][0] + bv.x;
            float v1 = acc[mt][nt][1] + bv.y;
            float v2 = acc[mt][nt][2] + bv.x;
            float v3 = acc[mt][nt][3] + bv.y;
            if (EPI == EPI_GELU) {
                v0 *= normcdff(v0); v1 *= normcdff(v1);
                v2 *= normcdff(v2); v3 *= normcdff(v3);
            }
            size_t o0 = (size_t)r0 * NTOT + cb;
            size_t o1 = (size_t)(r0 + 8) * NTOT + cb;
            if (EPI == EPI_RES) {
                float2 r0v = *(const float2*)(res + o0);
                float2 r1v = *(const float2*)(res + o1);
                v0 += r0v.x; v1 += r0v.y; v2 += r1v.x; v3 += r1v.y;
            }
            if (WF32) {
                float2 s0 = {v0, v1}, s1 = {v2, v3};
                *(float2*)(C + o0) = s0;
                *(float2*)(C + o1) = s1;
            }
            if (H16) {
                __half2 h0 = __floats2half2_rn(v0, v1);
                __half2 h1 = __floats2half2_rn(v2, v3);
                *(__half2*)(Ch + o0) = h0;
                *(__half2*)(Ch + o1) = h1;
            }
        }
    }
}

// ---------------- 512-thread hgemm, M=64 x N=256 tile (wave-friendly) -------
// 16 n-warps, warp tile 64x16. Same k-order per output -> identical numerics.
#define M64_BB (4 * 2560)                        // B base (halves)
#define M64_BYTES ((4 * 2560 + 4 * 8448) * 2)    // 88064 B

template <int NTOT, int K, int WF32, int H16, int EPI>
__global__ __launch_bounds__(512, 1)
void hgemm_m64(const __half* __restrict__ A, const __half* __restrict__ W,
               float* __restrict__ C, __half* __restrict__ Ch,
               const float* __restrict__ bias, const float* __restrict__ res) {
    extern __shared__ __half hsm[];
    const int tid = threadIdx.x;
    const int m0 = blockIdx.y * 64, n0 = blockIdx.x * 256;
    const int lane = tid & 31, wid = tid >> 5;
    const int wn0 = wid * 16;                 // 16 n-warps
    const int g = lane >> 2, tq = lane & 3;
    const uint32_t sb = smem_u32(hsm);

    float acc[4][2][4];
#pragma unroll
    for (int i = 0; i < 4; i++)
#pragma unroll
        for (int j = 0; j < 2; j++)
#pragma unroll
            for (int c = 0; c < 4; c++) acc[i][j][c] = 0.f;

    // A: 64 rows x 4 granules = 256 cpa16 (threads < 256)
    const int am  = tid >> 2;                 // 0..127 (use <64 via tid<256: 0..63)
    const int akg = tid & 3;
    const int bk  = tid >> 5;
    const int bg  = tid & 31;
    const __half* aptr = A + (size_t)(m0 + am) * K + akg * 8;
    const __half* wptr = W + (size_t)bk * NTOT + n0 + bg * 8;
    const uint32_t adst = sb + (uint32_t)(am * 40 + akg * 8) * 2;
    const uint32_t bdst = sb + (uint32_t)(M64_BB + bk * 264 + bg * 8) * 2;
    const bool aload = (tid < 256);

    const int NT = K / 32;
#pragma unroll 1
    for (int p = 0; p < 3; p++) {
        if (aload) cpa16(adst + (uint32_t)(p * 2560) * 2, aptr + (size_t)p * 32);
        uint32_t bd = bdst + (uint32_t)(p * 8448) * 2;
        const __half* wp = wptr + (size_t)p * 32 * NTOT;
        cpa16(bd, wp);
        cpa16(bd + (uint32_t)(16 * 264) * 2, wp + (size_t)16 * NTOT);
        CP_COMMIT();
    }

    const int a_r = lane & 15;
    const int a_c = (lane >> 4) * 8;

#pragma unroll 1
    for (int t = 0; t < NT; t++) {
        CP_WAIT2();
        __syncthreads();
        if (t + 3 < NT) {
            const int sn = (t + 3) & 3;
            if (aload) cpa16(adst + (uint32_t)(sn * 2560) * 2, aptr + (size_t)(t + 3) * 32);
            uint32_t bd = bdst + (uint32_t)(sn * 8448) * 2;
            const __half* wp = wptr + (size_t)(t + 3) * 32 * NTOT;
            cpa16(bd, wp);
            cpa16(bd + (uint32_t)(16 * 264) * 2, wp + (size_t)16 * NTOT);
        }
        CP_COMMIT();
        const int s = t & 3;
        const uint32_t as_ = sb + (uint32_t)(s * 2560) * 2;
        const uint32_t bs_ = sb + (uint32_t)(M64_BB + s * 8448) * 2;
#pragma unroll
        for (int ks = 0; ks < 2; ks++) {
            unsigned af[4][4], bf[2][2];
#pragma unroll
            for (int mt = 0; mt < 4; mt++)
                ldsm4(af[mt][0], af[mt][1], af[mt][2], af[mt][3],
                      as_ + (uint32_t)((mt * 16 + a_r) * 40 + ks * 16 + a_c) * 2);
            ldsm4t(bf[0][0], bf[0][1], bf[1][0], bf[1][1],
                   bs_ + (uint32_t)((ks * 16 + a_r) * 264 + wn0 + a_c) * 2);
#pragma unroll
            for (int mt = 0; mt < 4; mt++)
#pragma unroll
                for (int nt = 0; nt < 2; nt++)
                    mma_f16(acc[mt][nt], af[mt], bf[nt]);
        }
    }

    // ---- epilogue ----
#pragma unroll
    for (int mt = 0; mt < 4; mt++) {
        int r0 = m0 + mt * 16 + g;
#pragma unroll
        for (int nt = 0; nt < 2; nt++) {
            int cb = n0 + wn0 + nt * 8 + 2 * tq;
            float2 bv = *(const float2*)(bias + cb);
            float v0 = acc[mt][nt][0] + bv.x;
            float v1 = acc[mt][nt][1] + bv.y;
            float v2 = acc[mt][nt][2] + bv.x;
            float v3 = acc[mt][nt][3] + bv.y;
            if (EPI == EPI_GELU) {
                v0 *= normcdff(v0); v1 *= normcdff(v1);
                v2 *= normcdff(v2); v3 *= normcdff(v3);
            }
            size_t o0 = (size_t)r0 * NTOT + cb;
            size_t o1 = (size_t)(r0 + 8) * NTOT + cb;
            if (EPI == EPI_RES) {
                float2 r0v = *(const float2*)(res + o0);
                float2 r1v = *(const float2*)(res + o1);
                v0 += r0v.x; v1 += r0v.y; v2 += r1v.x; v3 += r1v.y;
            }
            if (WF32) {
                float2 s0 = {v0, v1}, s1 = {v2, v3};
                *(float2*)(C + o0) = s0;
                *(float2*)(C + o1) = s1;
            }
            if (H16) {
                __half2 h0 = __floats2half2_rn(v0, v1);
                __half2 h1 = __floats2half2_rn(v2, v3);
                *(__half2*)(Ch + o0) = h0;
                *(__half2*)(Ch + o1) = h1;
            }
        }
    }
}

// ---------------- context partials via mma: ctxp = k^T v ----------------
__global__ __launch_bounds__(256, 2)
void ctx_mma(const __half* __restrict__ qkvh, float* __restrict__ ctxp) {
    __shared__ __half Kt[32][136];
    __shared__ __half Vt[32][136];
    const int bh = blockIdx.x, split = blockIdx.y;
    const int b = bh >> 2, h = bh & 3;
    const int tid = threadIdx.x, lane = tid & 31, wid = tid >> 5;
    const int wm0 = (wid >> 2) * 64, wn0 = (wid & 3) * 32;
    const int g = lane >> 2, tq = lane & 3;
    const uint32_t kb = smem_u32(Kt), vb = smem_u32(Vt);

    float acc[4][4][4];
#pragma unroll
    for (int i = 0; i < 4; i++)
#pragma unroll
        for (int j = 0; j < 4; j++)
#pragma unroll
            for (int c = 0; c < 4; c++) acc[i][j][c] = 0.f;

    const int arA = lane & 7, acA = (lane >> 3) & 1, asA = (lane >> 4) & 1;
    const int a_r = lane & 15, a_c = (lane >> 4) * 8;

    for (int ch = 0; ch < (NN / CSPLIT) / 32; ch++) {
        int nb = split * (NN / CSPLIT) + ch * 32;
        if (ch) __syncthreads();
#pragma unroll
        for (int i = 0; i < 2; i++) {
            int idx = tid + i * 256;
            int row = idx >> 4, gc = idx & 15;
            size_t src = ((size_t)(b * NN + nb + row)) * 1536 + (size_t)h * DD + gc * 8;
            *(uint4*)&Kt[row][gc * 8] = *(const uint4*)(qkvh + src + 512);
            *(uint4*)&Vt[row][gc * 8] = *(const uint4*)(qkvh + src + 1024);
        }
        __syncthreads();
#pragma unroll
        for (int ks = 0; ks < 2; ks++) {
            unsigned af[4][4], bf[4][2];
#pragma unroll
            for (int mt = 0; mt < 4; mt++)
                ldsm4t(af[mt][0], af[mt][1], af[mt][2], af[mt][3],
                       kb + (uint32_t)((ks * 16 + arA + asA * 8) * 136 +
                                       wm0 + mt * 16 + acA * 8) * 2);
#pragma unroll
            for (int nq = 0; nq < 2; nq++)
                ldsm4t(bf[2 * nq][0], bf[2 * nq][1], bf[2 * nq + 1][0], bf[2 * nq + 1][1],
                       vb + (uint32_t)((ks * 16 + a_r) * 136 + wn0 + nq * 16 + a_c) * 2);
#pragma unroll
            for (int mt = 0; mt < 4; mt++)
#pragma unroll
                for (int nt = 0; nt < 4; nt++)
                    mma_f16(acc[mt][nt], af[mt], bf[nt]);
        }
    }
    float* outp = ctxp + ((size_t)split * 16 + bh) * (DD * DD);
#pragma unroll
    for (int mt = 0; mt < 4; mt++) {
        int d = wm0 + mt * 16 + g;
#pragma unroll
        for (int nt = 0; nt < 4; nt++) {
            int e = wn0 + nt * 8 + 2 * tq;
            float2 s0 = {acc[mt][nt][0], acc[mt][nt][1]};
            float2 s1 = {acc[mt][nt][2], acc[mt][nt][3]};
            *(float2*)(outp + (size_t)d * DD + e) = s0;
            *(float2*)(outp + (size_t)(d + 8) * DD + e) = s1;
        }
    }
}

__global__ void reduce_ctx(const float* __restrict__ ctxp, __half* __restrict__ ctxh) {
    int i = blockIdx.x * blockDim.x + threadIdx.x;
    float s = 0.f;
#pragma unroll
    for (int sp = 0; sp < CSPLIT; sp++) s += ctxp[(size_t)sp * (16 * DD * DD) + i];
    ctxh[i] = __float2half(s * SCALE);
}

// ---------------- attn = q @ (ctx*scale) via mma, fp16 out ----------------
#define ASM_BYTES (2 * 128 * 136 * 2)
__global__ __launch_bounds__(256, 2)
void attn_mma(const __half* __restrict__ qkvh, const __half* __restrict__ ctxh,
              __half* __restrict__ attnh) {
    extern __shared__ __half asmem[];
    __half* Qs = asmem;
    __half* Cs = asmem + 128 * 136;
    const int tile = blockIdx.x, bh = blockIdx.y;
    const int b = bh >> 2, h = bh & 3;
    const int tid = threadIdx.x, lane = tid & 31, wid = tid >> 5;
    const int wm0 = (wid >> 2) * 64, wn0 = (wid & 3) * 32;
    const int g = lane >> 2, tq = lane & 3;

#pragma unroll
    for (int i = 0; i < 8; i++) {
        int idx = tid + i * 256;
        int row = idx >> 4, gc = idx & 15;
        *(uint4*)&Qs[row * 136 + gc * 8] =
            *(const uint4*)(qkvh + ((size_t)(b * NN + tile * 128 + row)) * 1536 +
                            (size_t)h * DD + gc * 8);
        *(uint4*)&Cs[row * 136 + gc * 8] =
            *(const uint4*)(ctxh + (size_t)bh * (DD * DD) + (size_t)row * DD + gc * 8);
    }
    __syncthreads();

    float acc[4][4][4];
#pragma unroll
    for (int i = 0; i < 4; i++)
#pragma unroll
        for (int j = 0; j < 4; j++)
#pragma unroll
            for (int c = 0; c < 4; c++) acc[i][j][c] = 0.f;

    const uint32_t qb = smem_u32(Qs), cb2 = smem_u32(Cs);
    const int a_r = lane & 15, a_c = (lane >> 4) * 8;

#pragma unroll
    for (int ks = 0; ks < 8; ks++) {
        unsigned af[4][4], bf[4][2];
#pragma unroll
        for (int mt = 0; mt < 4; mt++)
            ldsm4(af[mt][0], af[mt][1], af[mt][2], af[mt][3],
                  qb + (uint32_t)((wm0 + mt * 16 + a_r) * 136 + ks * 16 + a_c) * 2);
#pragma unroll
        for (int nq = 0; nq < 2; nq++)
            ldsm4t(bf[2 * nq][0], bf[2 * nq][1], bf[2 * nq + 1][0], bf[2 * nq + 1][1],
                   cb2 + (uint32_t)((ks * 16 + a_r) * 136 + wn0 + nq * 16 + a_c) * 2);
#pragma unroll
        for (int mt = 0; mt < 4; mt++)
#pragma unroll
            for (int nt = 0; nt < 4; nt++)
                mma_f16(acc[mt][nt], af[mt], bf[nt]);
    }

#pragma unroll
    for (int mt = 0; mt < 4; mt++) {
        size_t r0 = (size_t)(b * NN + tile * 128 + wm0 + mt * 16 + g);
#pragma unroll
        for (int nt = 0; nt < 4; nt++) {
            int col = h * DD + wn0 + nt * 8 + 2 * tq;
            __half2 h0 = __floats2half2_rn(acc[mt][nt][0], acc[mt][nt][1]);
            __half2 h1 = __floats2half2_rn(acc[mt][nt][2], acc[mt][nt][3]);
            *(__half2*)(attnh + r0 * CC + col) = h0;
            *(__half2*)(attnh + (r0 + 8) * CC + col) = h1;
        }
    }
}

// ---------------- launch ----------------
extern "C" void kernel_launch(void* const* d_in, const int* in_sizes, int n_in,
                              void* d_out, int out_size) {
    const float* x       = (const float*)d_in[0];
    const float* norm1_w = (const float*)d_in[1];
    const float* norm1_b = (const float*)d_in[2];
    const float* qkv_w   = (const float*)d_in[3];
    const float* qkv_b   = (const float*)d_in[4];
    const float* lnk_w   = (const float*)d_in[5];
    const float* lnk_b   = (const float*)d_in[6];
    const float* lnv_w   = (const float*)d_in[7];
    const float* lnv_b   = (const float*)d_in[8];
    const float* proj_w  = (const float*)d_in[9];
    const float* proj_b  = (const float*)d_in[10];
    const float* norm2_w = (const float*)d_in[11];
    const float* norm2_b = (const float*)d_in[12];
    const float* mlp_w1  = (const float*)d_in[13];
    const float* mlp_b1  = (const float*)d_in[14];
    const float* mlp_w2  = (const float*)d_in[15];
    const float* mlp_b2  = (const float*)d_in[16];
    float* out = (float*)d_out;

    float  *x1, *ctxp;
    __half *xh, *qkvh, *attnh, *mlphh, *ctxh, *wh;
    cudaGetSymbolAddress((void**)&x1,    g_x1);
    cudaGetSymbolAddress((void**)&ctxp,  g_ctxp);
    cudaGetSymbolAddress((void**)&xh,    g_xh);
    cudaGetSymbolAddress((void**)&qkvh,  g_qkvh);
    cudaGetSymbolAddress((void**)&attnh, g_attnh);
    cudaGetSymbolAddress((void**)&mlphh, g_mlphh);
    cudaGetSymbolAddress((void**)&ctxh,  g_ctxh);
    cudaGetSymbolAddress((void**)&wh,    g_wh);

    cudaFuncSetAttribute(qkv512,
                         cudaFuncAttributeMaxDynamicSharedMemorySize, HSM_BYTES);
    cudaFuncSetAttribute(hgemm_m64<512, 512, 1, 0, EPI_RES>,
                         cudaFuncAttributeMaxDynamicSharedMemorySize, M64_BYTES);
    cudaFuncSetAttribute(hgemm512<2048, 512, 0, 1, EPI_GELU>,
                         cudaFuncAttributeMaxDynamicSharedMemorySize, HSM_BYTES);
    cudaFuncSetAttribute(hgemm_m64<512, 2048, 1, 0, EPI_RES>,
                         cudaFuncAttributeMaxDynamicSharedMemorySize, M64_BYTES);
    cudaFuncSetAttribute(attn_mma,
                         cudaFuncAttributeMaxDynamicSharedMemorySize, ASM_BYTES);

    // 0. all weights -> fp16 (one launch)
    f2h_all<<<3072, 256>>>(qkv_w, proj_w, mlp_w1, mlp_w2, wh);

    // 1. LN1 -> fp16
    ln_rows512<<<MTOK, 256>>>(x, xh, norm1_w, norm1_b);
    // 2. qkv = xn @ qkv_w + b, fused k/v LN, fp16 out
    qkv512<<<dim3(6, 256), 512, HSM_BYTES>>>(
        xh, wh + WH_QKV, qkvh, qkv_b, lnk_w, lnk_b, lnv_w, lnv_b);
    // 3. context = k^T v ; reduce * SCALE -> fp16
    ctx_mma<<<dim3(16, CSPLIT), 256>>>(qkvh, ctxp);
    reduce_ctx<<<1024, 256>>>(ctxp, ctxh);
    // 4. attn = q @ ctx -> fp16
    attn_mma<<<dim3(64, 16), 256, ASM_BYTES>>>(qkvh, ctxh, attnh);
    // 5. x1 = x + attn @ proj_w + b  (fp32, M64 wave-friendly tiles)
    hgemm_m64<512, 512, 1, 0, EPI_RES><<<dim3(2, 512), 512, M64_BYTES>>>(
        attnh, wh + WH_PROJ, x1, nullptr, proj_b, x);
    // 6. LN2 -> fp16
    ln_rows512<<<MTOK, 256>>>(x1, xh, norm2_w, norm2_b);
    // 7. mlp hidden = gelu(h @ w1 + b1)  (fp16 only)
    hgemm512<2048, 512, 0, 1, EPI_GELU><<<dim3(8, 256), 512, HSM_BYTES>>>(
        xh, wh + WH_MLP1, nullptr, mlphh, mlp_b1, nullptr);
    // 8. out = x1 + mlph @ w2 + b2  (fp32, M64 wave-friendly tiles)
    hgemm_m64<512, 2048, 1, 0, EPI_RES><<<dim3(2, 512), 512, M64_BYTES>>>(
        mlphh, wh + WH_MLP2, out, nullptr, mlp_b2, x1);
}

// round 14
// speedup vs baseline: 1.1502x; 1.1502x over previous
#include <cuda_runtime.h>
#include <cuda_fp16.h>
#include <cstdint>

// ---------------- problem constants ----------------
#define BB 4
#define NN 8192
#define CC 512
#define DD 128
#define HID 2048
#define MTOK 32768
#define EPS 1e-5f
#define SCALE 0.08838834764831845f   // 128^-0.5
#define CSPLIT 16

// ---------------- scratch ----------------
__device__ float  g_x1  [(size_t)MTOK * CC];          // fp32 residual
__device__ float  g_ctxp[(size_t)CSPLIT * 16 * DD * DD];
__device__ __half g_xh   [(size_t)MTOK * CC];         // LN1/LN2 out (fp16)
__device__ __half g_qkvh [(size_t)MTOK * 1536];       // fp16 q + LN'd k,v
__device__ __half g_attnh[(size_t)MTOK * CC];
__device__ __half g_mlphh[(size_t)MTOK * HID];
__device__ __half g_ctxh [(size_t)16 * DD * DD];
__device__ __half g_wh   [(size_t)3145728];           // all weights fp16

#define WH_QKV  0
#define WH_PROJ 786432
#define WH_MLP1 1048576
#define WH_MLP2 2097152

// ---------------- ptx helpers ----------------
__device__ __forceinline__ uint32_t smem_u32(const void* p) {
    uint32_t r;
    asm("{ .reg .u64 t; cvta.to.shared.u64 t, %1; cvt.u32.u64 %0, t; }" : "=r"(r) : "l"(p));
    return r;
}
__device__ __forceinline__ void mma_f16(float* d, const unsigned* a, const unsigned* b) {
    asm volatile(
        "mma.sync.aligned.m16n8k16.row.col.f32.f16.f16.f32 "
        "{%0,%1,%2,%3}, {%4,%5,%6,%7}, {%8,%9}, {%0,%1,%2,%3};"
        : "+f"(d[0]), "+f"(d[1]), "+f"(d[2]), "+f"(d[3])
        : "r"(a[0]), "r"(a[1]), "r"(a[2]), "r"(a[3]), "r"(b[0]), "r"(b[1]));
}
__device__ __forceinline__ void ldsm4(unsigned& r0, unsigned& r1, unsigned& r2, unsigned& r3, uint32_t a) {
    asm volatile("ldmatrix.sync.aligned.m8n8.x4.shared.b16 {%0,%1,%2,%3}, [%4];"
                 : "=r"(r0), "=r"(r1), "=r"(r2), "=r"(r3) : "r"(a));
}
__device__ __forceinline__ void ldsm4t(unsigned& r0, unsigned& r1, unsigned& r2, unsigned& r3, uint32_t a) {
    asm volatile("ldmatrix.sync.aligned.m8n8.x4.trans.shared.b16 {%0,%1,%2,%3}, [%4];"
                 : "=r"(r0), "=r"(r1), "=r"(r2), "=r"(r3) : "r"(a));
}
__device__ __forceinline__ void cpa16(uint32_t dst, const void* src) {
    asm volatile("cp.async.cg.shared.global [%0], [%1], 16;" :: "r"(dst), "l"(src));
}
#define CP_COMMIT() asm volatile("cp.async.commit_group;" ::: "memory")
#define CP_WAIT2()  asm volatile("cp.async.wait_group 2;" ::: "memory")

// ---------------- fused fp32 -> fp16 weight convert ----------------
__global__ void f2h_all(const float* __restrict__ a, const float* __restrict__ b,
                        const float* __restrict__ c, const float* __restrict__ d,
                        __half* __restrict__ out) {
    int i = (blockIdx.x * 256 + threadIdx.x) * 4;
    const float* src; int off;
    if (i < 786432)       { src = a; off = i; }
    else if (i < 1048576) { src = b; off = i - 786432; }
    else if (i < 2097152) { src = c; off = i - 1048576; }
    else                  { src = d; off = i - 2097152; }
    float4 v = *(const float4*)(src + off);
    __half2 h0 = __floats2half2_rn(v.x, v.y), h1 = __floats2half2_rn(v.z, v.w);
    uint2 u; u.x = *(unsigned*)&h0; u.y = *(unsigned*)&h1;
    *(uint2*)(out + i) = u;
}

// ---------------- LayerNorm over 512 (fp32 in, fp16 out) ----------------
__global__ void ln_rows512(const float* __restrict__ x, __half* __restrict__ y,
                           const float* __restrict__ w, const float* __restrict__ b) {
    int row = blockIdx.x;
    const float* xr = x + (size_t)row * CC;
    int t = threadIdx.x;
    float2 v = *(const float2*)(xr + 2 * t);
    float s = v.x + v.y, s2 = v.x * v.x + v.y * v.y;
#pragma unroll
    for (int o = 16; o > 0; o >>= 1) {
        s  += __shfl_xor_sync(0xffffffffu, s,  o);
        s2 += __shfl_xor_sync(0xffffffffu, s2, o);
    }
    __shared__ float sh[18];
    int wid = t >> 5, lane = t & 31;
    if (lane == 0) { sh[wid] = s; sh[wid + 8] = s2; }
    __syncthreads();
    if (t == 0) {
        float ts = 0.f, ts2 = 0.f;
#pragma unroll
        for (int i = 0; i < 8; i++) { ts += sh[i]; ts2 += sh[i + 8]; }
        float mu  = ts * (1.f / CC);
        float var = ts2 * (1.f / CC) - mu * mu;
        sh[16] = mu; sh[17] = rsqrtf(var + EPS);
    }
    __syncthreads();
    float mu = sh[16], inv = sh[17];
    float2 wv = *(const float2*)(w + 2 * t);
    float2 bv = *(const float2*)(b + 2 * t);
    __half2 o = __floats2half2_rn((v.x - mu) * inv * wv.x + bv.x,
                                  (v.y - mu) * inv * wv.y + bv.y);
    *(__half2*)(y + (size_t)row * CC + 2 * t) = o;
}

// ---------------- 512-thread GEMM mainloop ----------------
#define EPI_GELU 1
#define EPI_RES  2
#define HSM_BYTES ((4*128*40 + 4*32*264) * 2)

// ---------------- qkv GEMM, 512 threads, fused k/v LN epilogue --------------
__global__ __launch_bounds__(512, 1)
void qkv512(const __half* __restrict__ A, const __half* __restrict__ W,
            __half* __restrict__ Ch, const float* __restrict__ bias,
            const float* __restrict__ lnk_w, const float* __restrict__ lnk_b,
            const float* __restrict__ lnv_w, const float* __restrict__ lnv_b) {
    extern __shared__ __half hsm[];
    const int NTOT = 1536, K = 512;
    const int tid = threadIdx.x;
    const int m0 = blockIdx.y * 128, n0 = blockIdx.x * 256;
    const int lane = tid & 31, wid = tid >> 5;
    const int wm0 = (wid >> 3) * 64;
    const int wn0 = (wid & 7) * 32;
    const int g = lane >> 2, tq = lane & 3;
    const uint32_t sb = smem_u32(hsm);

    float acc[4][4][4];
#pragma unroll
    for (int i = 0; i < 4; i++)
#pragma unroll
        for (int j = 0; j < 4; j++)
#pragma unroll
            for (int c = 0; c < 4; c++) acc[i][j][c] = 0.f;

    const int am  = tid >> 2;
    const int akg = tid & 3;
    const int bk  = tid >> 5;
    const int bg  = tid & 31;
    const __half* aptr = A + (size_t)(m0 + am) * K + akg * 8;
    const __half* wptr = W + (size_t)bk * NTOT + n0 + bg * 8;
    const uint32_t adst = sb + (uint32_t)(am * 40 + akg * 8) * 2;
    const uint32_t bdst = sb + (uint32_t)(20480 + bk * 264 + bg * 8) * 2;

    const int NT = K / 32;
#pragma unroll 1
    for (int p = 0; p < 3; p++) {
        cpa16(adst + (uint32_t)(p * 5120) * 2, aptr + (size_t)p * 32);
        uint32_t bd = bdst + (uint32_t)(p * 8448) * 2;
        const __half* wp = wptr + (size_t)p * 32 * NTOT;
        cpa16(bd, wp);
        cpa16(bd + (uint32_t)(16 * 264) * 2, wp + (size_t)16 * NTOT);
        CP_COMMIT();
    }

    const int a_r = lane & 15;
    const int a_c = (lane >> 4) * 8;

#pragma unroll 1
    for (int t0 = 0; t0 < NT; t0 += 4) {
#pragma unroll
        for (int tt = 0; tt < 4; tt++) {
            const int t = t0 + tt;
            CP_WAIT2();
            __syncthreads();
            if (t + 3 < NT) {
                const int sn = (tt + 3) & 3;            // compile-time stage
                cpa16(adst + (uint32_t)(sn * 5120) * 2, aptr + (size_t)(t + 3) * 32);
                uint32_t bd = bdst + (uint32_t)(sn * 8448) * 2;
                const __half* wp = wptr + (size_t)(t + 3) * 32 * NTOT;
                cpa16(bd, wp);
                cpa16(bd + (uint32_t)(16 * 264) * 2, wp + (size_t)16 * NTOT);
            }
            CP_COMMIT();
            const int s = tt;                           // compile-time stage
            const uint32_t as_ = sb + (uint32_t)(s * 5120) * 2;
            const uint32_t bs_ = sb + (uint32_t)(20480 + s * 8448) * 2;
#pragma unroll
            for (int ks = 0; ks < 2; ks++) {
                unsigned af[4][4], bf[4][2];
#pragma unroll
                for (int mt = 0; mt < 4; mt++)
                    ldsm4(af[mt][0], af[mt][1], af[mt][2], af[mt][3],
                          as_ + (uint32_t)((wm0 + mt * 16 + a_r) * 40 + ks * 16 + a_c) * 2);
#pragma unroll
                for (int nq = 0; nq < 2; nq++)
                    ldsm4t(bf[2 * nq][0], bf[2 * nq][1], bf[2 * nq + 1][0], bf[2 * nq + 1][1],
                           bs_ + (uint32_t)((ks * 16 + a_r) * 264 + wn0 + nq * 16 + a_c) * 2);
#pragma unroll
                for (int mt = 0; mt < 4; mt++)
#pragma unroll
                    for (int nt = 0; nt < 4; nt++)
                        mma_f16(acc[mt][nt], af[mt], bf[nt]);
            }
        }
    }

    // ---- bias ----
#pragma unroll
    for (int mt = 0; mt < 4; mt++)
#pragma unroll
        for (int nt = 0; nt < 4; nt++) {
            int cb = n0 + wn0 + nt * 8 + 2 * tq;
            float2 bv = *(const float2*)(bias + cb);
            acc[mt][nt][0] += bv.x; acc[mt][nt][1] += bv.y;
            acc[mt][nt][2] += bv.x; acc[mt][nt][3] += bv.y;
        }

    // ---- fused per-head LN for k (x∈{2,3}) / v (x∈{4,5}) ----
    if (blockIdx.x >= 2) {
        const float* lw = (blockIdx.x < 4) ? lnk_w : lnv_w;
        const float* lb = (blockIdx.x < 4) ? lnk_b : lnv_b;
        float* red = (float*)hsm;        // [2 heads][128 rows][4 nwarps][2] = 8KB
        const int head = (wid >> 2) & 1;
        const int j = wid & 3;
        float ps[4][2], ps2[4][2];
#pragma unroll
        for (int mt = 0; mt < 4; mt++)
#pragma unroll
            for (int h2 = 0; h2 < 2; h2++) {
                float s = 0.f, s2 = 0.f;
#pragma unroll
                for (int nt = 0; nt < 4; nt++) {
                    float a = acc[mt][nt][2 * h2], b = acc[mt][nt][2 * h2 + 1];
                    s += a + b; s2 += a * a + b * b;
                }
                ps[mt][h2] = s; ps2[mt][h2] = s2;
            }
#pragma unroll
        for (int off = 1; off < 4; off <<= 1)
#pragma unroll
            for (int mt = 0; mt < 4; mt++)
#pragma unroll
                for (int h2 = 0; h2 < 2; h2++) {
                    ps[mt][h2]  += __shfl_xor_sync(0xffffffffu, ps[mt][h2],  off);
                    ps2[mt][h2] += __shfl_xor_sync(0xffffffffu, ps2[mt][h2], off);
                }
        __syncthreads();
        if (tq == 0) {
#pragma unroll
            for (int mt = 0; mt < 4; mt++)
#pragma unroll
                for (int h2 = 0; h2 < 2; h2++) {
                    int row = wm0 + mt * 16 + g + 8 * h2;
                    int idx = ((head * 128 + row) * 4 + j) * 2;
                    red[idx] = ps[mt][h2]; red[idx + 1] = ps2[mt][h2];
                }
        }
        __syncthreads();
#pragma unroll
        for (int mt = 0; mt < 4; mt++) {
            float mu[2], inv[2];
#pragma unroll
            for (int h2 = 0; h2 < 2; h2++) {
                int row = wm0 + mt * 16 + g + 8 * h2;
                int i0 = (head * 128 + row) * 8;
                float s  = red[i0] + red[i0 + 2] + red[i0 + 4] + red[i0 + 6];
                float s2 = red[i0 + 1] + red[i0 + 3] + red[i0 + 5] + red[i0 + 7];
                float m = s * (1.f / 128);
                mu[h2] = m;
                inv[h2] = rsqrtf(s2 * (1.f / 128) - m * m + EPS);
            }
#pragma unroll
            for (int nt = 0; nt < 4; nt++) {
                int ch = j * 32 + nt * 8 + 2 * tq;
                float2 lwv = *(const float2*)(lw + ch);
                float2 lbv = *(const float2*)(lb + ch);
                acc[mt][nt][0] = (acc[mt][nt][0] - mu[0]) * inv[0] * lwv.x + lbv.x;
                acc[mt][nt][1] = (acc[mt][nt][1] - mu[0]) * inv[0] * lwv.y + lbv.y;
                acc[mt][nt][2] = (acc[mt][nt][2] - mu[1]) * inv[1] * lwv.x + lbv.x;
                acc[mt][nt][3] = (acc[mt][nt][3] - mu[1]) * inv[1] * lwv.y + lbv.y;
            }
        }
    }

    // ---- fp16 store ----
#pragma unroll
    for (int mt = 0; mt < 4; mt++) {
        int r0 = m0 + wm0 + mt * 16 + g;
#pragma unroll
        for (int nt = 0; nt < 4; nt++) {
            int cb = n0 + wn0 + nt * 8 + 2 * tq;
            __half2 h0 = __floats2half2_rn(acc[mt][nt][0], acc[mt][nt][1]);
            __half2 h1 = __floats2half2_rn(acc[mt][nt][2], acc[mt][nt][3]);
            *(__half2*)(Ch + (size_t)r0 * NTOT + cb) = h0;
            *(__half2*)(Ch + (size_t)(r0 + 8) * NTOT + cb) = h1;
        }
    }
}

// ---------------- 512-thread generic hgemm (128x256 tile) -------------------
template <int NTOT, int K, int WF32, int H16, int EPI>
__global__ __launch_bounds__(512, 1)
void hgemm512(const __half* __restrict__ A, const __half* __restrict__ W,
              float* __restrict__ C, __half* __restrict__ Ch,
              const float* __restrict__ bias, const float* __restrict__ res) {
    extern __shared__ __half hsm[];
    const int tid = threadIdx.x;
    const int m0 = blockIdx.y * 128, n0 = blockIdx.x * 256;
    const int lane = tid & 31, wid = tid >> 5;
    const int wm0 = (wid >> 3) * 64;
    const int wn0 = (wid & 7) * 32;
    const int g = lane >> 2, tq = lane & 3;
    const uint32_t sb = smem_u32(hsm);

    float acc[4][4][4];
#pragma unroll
    for (int i = 0; i < 4; i++)
#pragma unroll
        for (int j = 0; j < 4; j++)
#pragma unroll
            for (int c = 0; c < 4; c++) acc[i][j][c] = 0.f;

    const int am  = tid >> 2;
    const int akg = tid & 3;
    const int bk  = tid >> 5;
    const int bg  = tid & 31;
    const __half* aptr = A + (size_t)(m0 + am) * K + akg * 8;
    const __half* wptr = W + (size_t)bk * NTOT + n0 + bg * 8;
    const uint32_t adst = sb + (uint32_t)(am * 40 + akg * 8) * 2;
    const uint32_t bdst = sb + (uint32_t)(20480 + bk * 264 + bg * 8) * 2;

    const int NT = K / 32;
#pragma unroll 1
    for (int p = 0; p < 3; p++) {
        cpa16(adst + (uint32_t)(p * 5120) * 2, aptr + (size_t)p * 32);
        uint32_t bd = bdst + (uint32_t)(p * 8448) * 2;
        const __half* wp = wptr + (size_t)p * 32 * NTOT;
        cpa16(bd, wp);
        cpa16(bd + (uint32_t)(16 * 264) * 2, wp + (size_t)16 * NTOT);
        CP_COMMIT();
    }

    const int a_r = lane & 15;
    const int a_c = (lane >> 4) * 8;

#pragma unroll 1
    for (int t0 = 0; t0 < NT; t0 += 4) {
#pragma unroll
        for (int tt = 0; tt < 4; tt++) {
            const int t = t0 + tt;
            CP_WAIT2();
            __syncthreads();
            if (t + 3 < NT) {
                const int sn = (tt + 3) & 3;            // compile-time stage
                cpa16(adst + (uint32_t)(sn * 5120) * 2, aptr + (size_t)(t + 3) * 32);
                uint32_t bd = bdst + (uint32_t)(sn * 8448) * 2;
                const __half* wp = wptr + (size_t)(t + 3) * 32 * NTOT;
                cpa16(bd, wp);
                cpa16(bd + (uint32_t)(16 * 264) * 2, wp + (size_t)16 * NTOT);
            }
            CP_COMMIT();
            const int s = tt;                           // compile-time stage
            const uint32_t as_ = sb + (uint32_t)(s * 5120) * 2;
            const uint32_t bs_ = sb + (uint32_t)(20480 + s * 8448) * 2;
#pragma unroll
            for (int ks = 0; ks < 2; ks++) {
                unsigned af[4][4], bf[4][2];
#pragma unroll
                for (int mt = 0; mt < 4; mt++)
                    ldsm4(af[mt][0], af[mt][1], af[mt][2], af[mt][3],
                          as_ + (uint32_t)((wm0 + mt * 16 + a_r) * 40 + ks * 16 + a_c) * 2);
#pragma unroll
                for (int nq = 0; nq < 2; nq++)
                    ldsm4t(bf[2 * nq][0], bf[2 * nq][1], bf[2 * nq + 1][0], bf[2 * nq + 1][1],
                           bs_ + (uint32_t)((ks * 16 + a_r) * 264 + wn0 + nq * 16 + a_c) * 2);
#pragma unroll
                for (int mt = 0; mt < 4; mt++)
#pragma unroll
                    for (int nt = 0; nt < 4; nt++)
                        mma_f16(acc[mt][nt], af[mt], bf[nt]);
            }
        }
    }

#pragma unroll
    for (int mt = 0; mt < 4; mt++) {
        int r0 = m0 + wm0 + mt * 16 + g;
#pragma unroll
        for (int nt = 0; nt < 4; nt++) {
            int cb = n0 + wn0 + nt * 8 + 2 * tq;
            float2 bv = *(const float2*)(bias + cb);
            float v0 = acc[mt][nt][0] + bv.x;
            float v1 = acc[mt][nt][1] + bv.y;
            float v2 = acc[mt][nt][2] + bv.x;
            float v3 = acc[mt][nt][3] + bv.y;
            if (EPI == EPI_GELU) {
                v0 *= normcdff(v0); v1 *= normcdff(v1);
                v2 *= normcdff(v2); v3 *= normcdff(v3);
            }
            size_t o0 = (size_t)r0 * NTOT + cb;
            size_t o1 = (size_t)(r0 + 8) * NTOT + cb;
            if (EPI == EPI_RES) {
                float2 r0v = *(const float2*)(res + o0);
                float2 r1v = *(const float2*)(res + o1);
                v0 += r0v.x; v1 += r0v.y; v2 += r1v.x; v3 += r1v.y;
            }
            if (WF32) {
                float2 s0 = {v0, v1}, s1 = {v2, v3};
                *(float2*)(C + o0) = s0;
                *(float2*)(C + o1) = s1;
            }
            if (H16) {
                __half2 h0 = __floats2half2_rn(v0, v1);
                __half2 h1 = __floats2half2_rn(v2, v3);
                *(__half2*)(Ch + o0) = h0;
                *(__half2*)(Ch + o1) = h1;
            }
        }
    }
}

// ---------------- context partials via mma: ctxp = k^T v ----------------
__global__ __launch_bounds__(256, 2)
void ctx_mma(const __half* __restrict__ qkvh, float* __restrict__ ctxp) {
    __shared__ __half Kt[32][136];
    __shared__ __half Vt[32][136];
    const int bh = blockIdx.x, split = blockIdx.y;
    const int b = bh >> 2, h = bh & 3;
    const int tid = threadIdx.x, lane = tid & 31, wid = tid >> 5;
    const int wm0 = (wid >> 2) * 64, wn0 = (wid & 3) * 32;
    const int g = lane >> 2, tq = lane & 3;
    const uint32_t kb = smem_u32(Kt), vb = smem_u32(Vt);

    float acc[4][4][4];
#pragma unroll
    for (int i = 0; i < 4; i++)
#pragma unroll
        for (int j = 0; j < 4; j++)
#pragma unroll
            for (int c = 0; c < 4; c++) acc[i][j][c] = 0.f;

    const int arA = lane & 7, acA = (lane >> 3) & 1, asA = (lane >> 4) & 1;
    const int a_r = lane & 15, a_c = (lane >> 4) * 8;

    for (int ch = 0; ch < (NN / CSPLIT) / 32; ch++) {
        int nb = split * (NN / CSPLIT) + ch * 32;
        if (ch) __syncthreads();
#pragma unroll
        for (int i = 0; i < 2; i++) {
            int idx = tid + i * 256;
            int row = idx >> 4, gc = idx & 15;
            size_t src = ((size_t)(b * NN + nb + row)) * 1536 + (size_t)h * DD + gc * 8;
            *(uint4*)&Kt[row][gc * 8] = *(const uint4*)(qkvh + src + 512);
            *(uint4*)&Vt[row][gc * 8] = *(const uint4*)(qkvh + src + 1024);
        }
        __syncthreads();
#pragma unroll
        for (int ks = 0; ks < 2; ks++) {
            unsigned af[4][4], bf[4][2];
#pragma unroll
            for (int mt = 0; mt < 4; mt++)
                ldsm4t(af[mt][0], af[mt][1], af[mt][2], af[mt][3],
                       kb + (uint32_t)((ks * 16 + arA + asA * 8) * 136 +
                                       wm0 + mt * 16 + acA * 8) * 2);
#pragma unroll
            for (int nq = 0; nq < 2; nq++)
                ldsm4t(bf[2 * nq][0], bf[2 * nq][1], bf[2 * nq + 1][0], bf[2 * nq + 1][1],
                       vb + (uint32_t)((ks * 16 + a_r) * 136 + wn0 + nq * 16 + a_c) * 2);
#pragma unroll
            for (int mt = 0; mt < 4; mt++)
#pragma unroll
                for (int nt = 0; nt < 4; nt++)
                    mma_f16(acc[mt][nt], af[mt], bf[nt]);
        }
    }
    float* outp = ctxp + ((size_t)split * 16 + bh) * (DD * DD);
#pragma unroll
    for (int mt = 0; mt < 4; mt++) {
        int d = wm0 + mt * 16 + g;
#pragma unroll
        for (int nt = 0; nt < 4; nt++) {
            int e = wn0 + nt * 8 + 2 * tq;
            float2 s0 = {acc[mt][nt][0], acc[mt][nt][1]};
            float2 s1 = {acc[mt][nt][2], acc[mt][nt][3]};
            *(float2*)(outp + (size_t)d * DD + e) = s0;
            *(float2*)(outp + (size_t)(d + 8) * DD + e) = s1;
        }
    }
}

__global__ void reduce_ctx(const float* __restrict__ ctxp, __half* __restrict__ ctxh) {
    int i = blockIdx.x * blockDim.x + threadIdx.x;
    float s = 0.f;
#pragma unroll
    for (int sp = 0; sp < CSPLIT; sp++) s += ctxp[(size_t)sp * (16 * DD * DD) + i];
    ctxh[i] = __float2half(s * SCALE);
}

// ---------------- attn = q @ (ctx*scale) via mma, fp16 out ----------------
#define ASM_BYTES (2 * 128 * 136 * 2)
__global__ __launch_bounds__(256, 2)
void attn_mma(const __half* __restrict__ qkvh, const __half* __restrict__ ctxh,
              __half* __restrict__ attnh) {
    extern __shared__ __half asmem[];
    __half* Qs = asmem;
    __half* Cs = asmem + 128 * 136;
    const int tile = blockIdx.x, bh = blockIdx.y;
    const int b = bh >> 2, h = bh & 3;
    const int tid = threadIdx.x, lane = tid & 31, wid = tid >> 5;
    const int wm0 = (wid >> 2) * 64, wn0 = (wid & 3) * 32;
    const int g = lane >> 2, tq = lane & 3;

#pragma unroll
    for (int i = 0; i < 8; i++) {
        int idx = tid + i * 256;
        int row = idx >> 4, gc = idx & 15;
        *(uint4*)&Qs[row * 136 + gc * 8] =
            *(const uint4*)(qkvh + ((size_t)(b * NN + tile * 128 + row)) * 1536 +
                            (size_t)h * DD + gc * 8);
        *(uint4*)&Cs[row * 136 + gc * 8] =
            *(const uint4*)(ctxh + (size_t)bh * (DD * DD) + (size_t)row * DD + gc * 8);
    }
    __syncthreads();

    float acc[4][4][4];
#pragma unroll
    for (int i = 0; i < 4; i++)
#pragma unroll
        for (int j = 0; j < 4; j++)
#pragma unroll
            for (int c = 0; c < 4; c++) acc[i][j][c] = 0.f;

    const uint32_t qb = smem_u32(Qs), cb2 = smem_u32(Cs);
    const int a_r = lane & 15, a_c = (lane >> 4) * 8;

#pragma unroll
    for (int ks = 0; ks < 8; ks++) {
        unsigned af[4][4], bf[4][2];
#pragma unroll
        for (int mt = 0; mt < 4; mt++)
            ldsm4(af[mt][0], af[mt][1], af[mt][2], af[mt][3],
                  qb + (uint32_t)((wm0 + mt * 16 + a_r) * 136 + ks * 16 + a_c) * 2);
#pragma unroll
        for (int nq = 0; nq < 2; nq++)
            ldsm4t(bf[2 * nq][0], bf[2 * nq][1], bf[2 * nq + 1][0], bf[2 * nq + 1][1],
                   cb2 + (uint32_t)((ks * 16 + a_r) * 136 + wn0 + nq * 16 + a_c) * 2);
#pragma unroll
        for (int mt = 0; mt < 4; mt++)
#pragma unroll
            for (int nt = 0; nt < 4; nt++)
                mma_f16(acc[mt][nt], af[mt], bf[nt]);
    }

#pragma unroll
    for (int mt = 0; mt < 4; mt++) {
        size_t r0 = (size_t)(b * NN + tile * 128 + wm0 + mt * 16 + g);
#pragma unroll
        for (int nt = 0; nt < 4; nt++) {
            int col = h * DD + wn0 + nt * 8 + 2 * tq;
            __half2 h0 = __floats2half2_rn(acc[mt][nt][0], acc[mt][nt][1]);
            __half2 h1 = __floats2half2_rn(acc[mt][nt][2], acc[mt][nt][3]);
            *(__half2*)(attnh + r0 * CC + col) = h0;
            *(__half2*)(attnh + (r0 + 8) * CC + col) = h1;
        }
    }
}

// ---------------- launch ----------------
extern "C" void kernel_launch(void* const* d_in, const int* in_sizes, int n_in,
                              void* d_out, int out_size) {
    const float* x       = (const float*)d_in[0];
    const float* norm1_w = (const float*)d_in[1];
    const float* norm1_b = (const float*)d_in[2];
    const float* qkv_w   = (const float*)d_in[3];
    const float* qkv_b   = (const float*)d_in[4];
    const float* lnk_w   = (const float*)d_in[5];
    const float* lnk_b   = (const float*)d_in[6];
    const float* lnv_w   = (const float*)d_in[7];
    const float* lnv_b   = (const float*)d_in[8];
    const float* proj_w  = (const float*)d_in[9];
    const float* proj_b  = (const float*)d_in[10];
    const float* norm2_w = (const float*)d_in[11];
    const float* norm2_b = (const float*)d_in[12];
    const float* mlp_w1  = (const float*)d_in[13];
    const float* mlp_b1  = (const float*)d_in[14];
    const float* mlp_w2  = (const float*)d_in[15];
    const float* mlp_b2  = (const float*)d_in[16];
    float* out = (float*)d_out;

    float  *x1, *ctxp;
    __half *xh, *qkvh, *attnh, *mlphh, *ctxh, *wh;
    cudaGetSymbolAddress((void**)&x1,    g_x1);
    cudaGetSymbolAddress((void**)&ctxp,  g_ctxp);
    cudaGetSymbolAddress((void**)&xh,    g_xh);
    cudaGetSymbolAddress((void**)&qkvh,  g_qkvh);
    cudaGetSymbolAddress((void**)&attnh, g_attnh);
    cudaGetSymbolAddress((void**)&mlphh, g_mlphh);
    cudaGetSymbolAddress((void**)&ctxh,  g_ctxh);
    cudaGetSymbolAddress((void**)&wh,    g_wh);

    cudaFuncSetAttribute(qkv512,
                         cudaFuncAttributeMaxDynamicSharedMemorySize, HSM_BYTES);
    cudaFuncSetAttribute(hgemm512<512, 512, 1, 0, EPI_RES>,
                         cudaFuncAttributeMaxDynamicSharedMemorySize, HSM_BYTES);
    cudaFuncSetAttribute(hgemm512<2048, 512, 0, 1, EPI_GELU>,
                         cudaFuncAttributeMaxDynamicSharedMemorySize, HSM_BYTES);
    cudaFuncSetAttribute(hgemm512<512, 2048, 1, 0, EPI_RES>,
                         cudaFuncAttributeMaxDynamicSharedMemorySize, HSM_BYTES);
    cudaFuncSetAttribute(attn_mma,
                         cudaFuncAttributeMaxDynamicSharedMemorySize, ASM_BYTES);

    // 0. all weights -> fp16 (one launch)
    f2h_all<<<3072, 256>>>(qkv_w, proj_w, mlp_w1, mlp_w2, wh);

    // 1. LN1 -> fp16
    ln_rows512<<<MTOK, 256>>>(x, xh, norm1_w, norm1_b);
    // 2. qkv = xn @ qkv_w + b, fused k/v LN, fp16 out
    qkv512<<<dim3(6, 256), 512, HSM_BYTES>>>(
        xh, wh + WH_QKV, qkvh, qkv_b, lnk_w, lnk_b, lnv_w, lnv_b);
    // 3. context = k^T v ; reduce * SCALE -> fp16
    ctx_mma<<<dim3(16, CSPLIT), 256>>>(qkvh, ctxp);
    reduce_ctx<<<1024, 256>>>(ctxp, ctxh);
    // 4. attn = q @ ctx -> fp16
    attn_mma<<<dim3(64, 16), 256, ASM_BYTES>>>(qkvh, ctxh, attnh);
    // 5. x1 = x + attn @ proj_w + b  (fp32)
    hgemm512<512, 512, 1, 0, EPI_RES><<<dim3(2, 256), 512, HSM_BYTES>>>(
        attnh, wh + WH_PROJ, x1, nullptr, proj_b, x);
    // 6. LN2 -> fp16
    ln_rows512<<<MTOK, 256>>>(x1, xh, norm2_w, norm2_b);
    // 7. mlp hidden = gelu(h @ w1 + b1)  (fp16 only)
    hgemm512<2048, 512, 0, 1, EPI_GELU><<<dim3(8, 256), 512, HSM_BYTES>>>(
        xh, wh + WH_MLP1, nullptr, mlphh, mlp_b1, nullptr);
    // 8. out = x1 + mlph @ w2 + b2  (fp32)
    hgemm512<512, 2048, 1, 0, EPI_RES><<<dim3(2, 256), 512, HSM_BYTES>>>(
        mlphh, wh + WH_MLP2, out, nullptr, mlp_b2, x1);
}

// round 15
// speedup vs baseline: 1.1855x; 1.0307x over previous
#include <cuda_runtime.h>
#include <cuda_fp16.h>
#include <cstdint>

// ---------------- problem constants ----------------
#define BB 4
#define NN 8192
#define CC 512
#define DD 128
#define HID 2048
#define MTOK 32768
#define EPS 1e-5f
#define SCALE 0.08838834764831845f   // 128^-0.5
#define CSPLIT 16

// ---------------- scratch ----------------
__device__ float  g_x1  [(size_t)MTOK * CC];          // fp32 residual
__device__ float  g_ctxp[(size_t)CSPLIT * 16 * DD * DD];
__device__ __half g_xh   [(size_t)MTOK * CC];         // LN1/LN2 out (fp16)
__device__ __half g_qkvh [(size_t)MTOK * 1536];       // fp16 q + LN'd k,v
__device__ __half g_attnh[(size_t)MTOK * CC];
__device__ __half g_mlphh[(size_t)MTOK * HID];
__device__ __half g_ctxh [(size_t)16 * DD * DD];
__device__ __half g_wh   [(size_t)3145728];           // all weights fp16

#define WH_QKV  0
#define WH_PROJ 786432
#define WH_MLP1 1048576
#define WH_MLP2 2097152

// ---------------- ptx helpers ----------------
__device__ __forceinline__ uint32_t smem_u32(const void* p) {
    uint32_t r;
    asm("{ .reg .u64 t; cvta.to.shared.u64 t, %1; cvt.u32.u64 %0, t; }" : "=r"(r) : "l"(p));
    return r;
}
__device__ __forceinline__ void mma_f16(float* d, const unsigned* a, const unsigned* b) {
    asm volatile(
        "mma.sync.aligned.m16n8k16.row.col.f32.f16.f16.f32 "
        "{%0,%1,%2,%3}, {%4,%5,%6,%7}, {%8,%9}, {%0,%1,%2,%3};"
        : "+f"(d[0]), "+f"(d[1]), "+f"(d[2]), "+f"(d[3])
        : "r"(a[0]), "r"(a[1]), "r"(a[2]), "r"(a[3]), "r"(b[0]), "r"(b[1]));
}
__device__ __forceinline__ void ldsm4(unsigned& r0, unsigned& r1, unsigned& r2, unsigned& r3, uint32_t a) {
    asm volatile("ldmatrix.sync.aligned.m8n8.x4.shared.b16 {%0,%1,%2,%3}, [%4];"
                 : "=r"(r0), "=r"(r1), "=r"(r2), "=r"(r3) : "r"(a));
}
__device__ __forceinline__ void ldsm4t(unsigned& r0, unsigned& r1, unsigned& r2, unsigned& r3, uint32_t a) {
    asm volatile("ldmatrix.sync.aligned.m8n8.x4.trans.shared.b16 {%0,%1,%2,%3}, [%4];"
                 : "=r"(r0), "=r"(r1), "=r"(r2), "=r"(r3) : "r"(a));
}
__device__ __forceinline__ void cpa16(uint32_t dst, const void* src) {
    asm volatile("cp.async.cg.shared.global [%0], [%1], 16;" :: "r"(dst), "l"(src));
}
#define CP_COMMIT() asm volatile("cp.async.commit_group;" ::: "memory")
#define CP_WAIT2()  asm volatile("cp.async.wait_group 2;" ::: "memory")

// ---------------- fused fp32 -> fp16 weight convert ----------------
__global__ void f2h_all(const float* __restrict__ a, const float* __restrict__ b,
                        const float* __restrict__ c, const float* __restrict__ d,
                        __half* __restrict__ out) {
    int i = (blockIdx.x * 256 + threadIdx.x) * 4;
    const float* src; int off;
    if (i < 786432)       { src = a; off = i; }
    else if (i < 1048576) { src = b; off = i - 786432; }
    else if (i < 2097152) { src = c; off = i - 1048576; }
    else                  { src = d; off = i - 2097152; }
    float4 v = *(const float4*)(src + off);
    __half2 h0 = __floats2half2_rn(v.x, v.y), h1 = __floats2half2_rn(v.z, v.w);
    uint2 u; u.x = *(unsigned*)&h0; u.y = *(unsigned*)&h1;
    *(uint2*)(out + i) = u;
}

// ---------------- LayerNorm over 512 (fp32 in, fp16 out) ----------------
__global__ void ln_rows512(const float* __restrict__ x, __half* __restrict__ y,
                           const float* __restrict__ w, const float* __restrict__ b) {
    int row = blockIdx.x;
    const float* xr = x + (size_t)row * CC;
    int t = threadIdx.x;
    float2 v = *(const float2*)(xr + 2 * t);
    float s = v.x + v.y, s2 = v.x * v.x + v.y * v.y;
#pragma unroll
    for (int o = 16; o > 0; o >>= 1) {
        s  += __shfl_xor_sync(0xffffffffu, s,  o);
        s2 += __shfl_xor_sync(0xffffffffu, s2, o);
    }
    __shared__ float sh[18];
    int wid = t >> 5, lane = t & 31;
    if (lane == 0) { sh[wid] = s; sh[wid + 8] = s2; }
    __syncthreads();
    if (t == 0) {
        float ts = 0.f, ts2 = 0.f;
#pragma unroll
        for (int i = 0; i < 8; i++) { ts += sh[i]; ts2 += sh[i + 8]; }
        float mu  = ts * (1.f / CC);
        float var = ts2 * (1.f / CC) - mu * mu;
        sh[16] = mu; sh[17] = rsqrtf(var + EPS);
    }
    __syncthreads();
    float mu = sh[16], inv = sh[17];
    float2 wv = *(const float2*)(w + 2 * t);
    float2 bv = *(const float2*)(b + 2 * t);
    __half2 o = __floats2half2_rn((v.x - mu) * inv * wv.x + bv.x,
                                  (v.y - mu) * inv * wv.y + bv.y);
    *(__half2*)(y + (size_t)row * CC + 2 * t) = o;
}

// ---------------- 512-thread GEMM mainloop ----------------
#define EPI_GELU 1
#define EPI_RES  2
#define HSM_BYTES ((4*128*40 + 4*32*264) * 2)

// ---------------- qkv GEMM, 512 threads, fused k/v LN epilogue --------------
__global__ __launch_bounds__(512, 1)
void qkv512(const __half* __restrict__ A, const __half* __restrict__ W,
            __half* __restrict__ Ch, const float* __restrict__ bias,
            const float* __restrict__ lnk_w, const float* __restrict__ lnk_b,
            const float* __restrict__ lnv_w, const float* __restrict__ lnv_b) {
    extern __shared__ __half hsm[];
    const int NTOT = 1536, K = 512;
    const int tid = threadIdx.x;
    const int m0 = blockIdx.y * 128, n0 = blockIdx.x * 256;
    const int lane = tid & 31, wid = tid >> 5;
    const int wm0 = (wid >> 3) * 64;
    const int wn0 = (wid & 7) * 32;
    const int g = lane >> 2, tq = lane & 3;
    const uint32_t sb = smem_u32(hsm);

    float acc[4][4][4];
#pragma unroll
    for (int i = 0; i < 4; i++)
#pragma unroll
        for (int j = 0; j < 4; j++)
#pragma unroll
            for (int c = 0; c < 4; c++) acc[i][j][c] = 0.f;

    const int am  = tid >> 2;
    const int akg = tid & 3;
    const int bk  = tid >> 5;
    const int bg  = tid & 31;
    const __half* aptr = A + (size_t)(m0 + am) * K + akg * 8;
    const __half* wptr = W + (size_t)bk * NTOT + n0 + bg * 8;
    const uint32_t adst = sb + (uint32_t)(am * 40 + akg * 8) * 2;
    const uint32_t bdst = sb + (uint32_t)(20480 + bk * 264 + bg * 8) * 2;

    const int NT = K / 32;
#pragma unroll 1
    for (int p = 0; p < 3; p++) {
        cpa16(adst + (uint32_t)(p * 5120) * 2, aptr + (size_t)p * 32);
        uint32_t bd = bdst + (uint32_t)(p * 8448) * 2;
        const __half* wp = wptr + (size_t)p * 32 * NTOT;
        cpa16(bd, wp);
        cpa16(bd + (uint32_t)(16 * 264) * 2, wp + (size_t)16 * NTOT);
        CP_COMMIT();
    }

    const int a_r = lane & 15;
    const int a_c = (lane >> 4) * 8;

#pragma unroll 1
    for (int t0 = 0; t0 < NT; t0 += 4) {
#pragma unroll
        for (int tt = 0; tt < 4; tt++) {
            const int t = t0 + tt;
            CP_WAIT2();
            __syncthreads();
            if (t + 3 < NT) {
                const int sn = (tt + 3) & 3;
                cpa16(adst + (uint32_t)(sn * 5120) * 2, aptr + (size_t)(t + 3) * 32);
                uint32_t bd = bdst + (uint32_t)(sn * 8448) * 2;
                const __half* wp = wptr + (size_t)(t + 3) * 32 * NTOT;
                cpa16(bd, wp);
                cpa16(bd + (uint32_t)(16 * 264) * 2, wp + (size_t)16 * NTOT);
            }
            CP_COMMIT();
            const int s = tt;
            const uint32_t as_ = sb + (uint32_t)(s * 5120) * 2;
            const uint32_t bs_ = sb + (uint32_t)(20480 + s * 8448) * 2;
#pragma unroll
            for (int ks = 0; ks < 2; ks++) {
                unsigned af[4][4], bf[4][2];
#pragma unroll
                for (int mt = 0; mt < 4; mt++)
                    ldsm4(af[mt][0], af[mt][1], af[mt][2], af[mt][3],
                          as_ + (uint32_t)((wm0 + mt * 16 + a_r) * 40 + ks * 16 + a_c) * 2);
#pragma unroll
                for (int nq = 0; nq < 2; nq++)
                    ldsm4t(bf[2 * nq][0], bf[2 * nq][1], bf[2 * nq + 1][0], bf[2 * nq + 1][1],
                           bs_ + (uint32_t)((ks * 16 + a_r) * 264 + wn0 + nq * 16 + a_c) * 2);
#pragma unroll
                for (int mt = 0; mt < 4; mt++)
#pragma unroll
                    for (int nt = 0; nt < 4; nt++)
                        mma_f16(acc[mt][nt], af[mt], bf[nt]);
            }
        }
    }

    // ---- bias ----
#pragma unroll
    for (int mt = 0; mt < 4; mt++)
#pragma unroll
        for (int nt = 0; nt < 4; nt++) {
            int cb = n0 + wn0 + nt * 8 + 2 * tq;
            float2 bv = *(const float2*)(bias + cb);
            acc[mt][nt][0] += bv.x; acc[mt][nt][1] += bv.y;
            acc[mt][nt][2] += bv.x; acc[mt][nt][3] += bv.y;
        }

    // ---- fused per-head LN for k (x∈{2,3}) / v (x∈{4,5}) ----
    if (blockIdx.x >= 2) {
        const float* lw = (blockIdx.x < 4) ? lnk_w : lnv_w;
        const float* lb = (blockIdx.x < 4) ? lnk_b : lnv_b;
        float* red = (float*)hsm;        // [2 heads][128 rows][4 nwarps][2] = 8KB
        const int head = (wid >> 2) & 1;
        const int j = wid & 3;
        float ps[4][2], ps2[4][2];
#pragma unroll
        for (int mt = 0; mt < 4; mt++)
#pragma unroll
            for (int h2 = 0; h2 < 2; h2++) {
                float s = 0.f, s2 = 0.f;
#pragma unroll
                for (int nt = 0; nt < 4; nt++) {
                    float a = acc[mt][nt][2 * h2], b = acc[mt][nt][2 * h2 + 1];
                    s += a + b; s2 += a * a + b * b;
                }
                ps[mt][h2] = s; ps2[mt][h2] = s2;
            }
#pragma unroll
        for (int off = 1; off < 4; off <<= 1)
#pragma unroll
            for (int mt = 0; mt < 4; mt++)
#pragma unroll
                for (int h2 = 0; h2 < 2; h2++) {
                    ps[mt][h2]  += __shfl_xor_sync(0xffffffffu, ps[mt][h2],  off);
                    ps2[mt][h2] += __shfl_xor_sync(0xffffffffu, ps2[mt][h2], off);
                }
        __syncthreads();
        if (tq == 0) {
#pragma unroll
            for (int mt = 0; mt < 4; mt++)
#pragma unroll
                for (int h2 = 0; h2 < 2; h2++) {
                    int row = wm0 + mt * 16 + g + 8 * h2;
                    int idx = ((head * 128 + row) * 4 + j) * 2;
                    red[idx] = ps[mt][h2]; red[idx + 1] = ps2[mt][h2];
                }
        }
        __syncthreads();
#pragma unroll
        for (int mt = 0; mt < 4; mt++) {
            float mu[2], inv[2];
#pragma unroll
            for (int h2 = 0; h2 < 2; h2++) {
                int row = wm0 + mt * 16 + g + 8 * h2;
                int i0 = (head * 128 + row) * 8;
                float s  = red[i0] + red[i0 + 2] + red[i0 + 4] + red[i0 + 6];
                float s2 = red[i0 + 1] + red[i0 + 3] + red[i0 + 5] + red[i0 + 7];
                float m = s * (1.f / 128);
                mu[h2] = m;
                inv[h2] = rsqrtf(s2 * (1.f / 128) - m * m + EPS);
            }
#pragma unroll
            for (int nt = 0; nt < 4; nt++) {
                int ch = j * 32 + nt * 8 + 2 * tq;
                float2 lwv = *(const float2*)(lw + ch);
                float2 lbv = *(const float2*)(lb + ch);
                acc[mt][nt][0] = (acc[mt][nt][0] - mu[0]) * inv[0] * lwv.x + lbv.x;
                acc[mt][nt][1] = (acc[mt][nt][1] - mu[0]) * inv[0] * lwv.y + lbv.y;
                acc[mt][nt][2] = (acc[mt][nt][2] - mu[1]) * inv[1] * lwv.x + lbv.x;
                acc[mt][nt][3] = (acc[mt][nt][3] - mu[1]) * inv[1] * lwv.y + lbv.y;
            }
        }
    }

    // ---- smem-staged fp16 store (128B-coalesced) ----
    __syncthreads();                 // pipeline smem + LN red reads done
#pragma unroll
    for (int mt = 0; mt < 4; mt++) {
        int row = wm0 + mt * 16 + g;
#pragma unroll
        for (int nt = 0; nt < 4; nt++) {
            int col = wn0 + nt * 8 + 2 * tq;
            __half2 h0 = __floats2half2_rn(acc[mt][nt][0], acc[mt][nt][1]);
            __half2 h1 = __floats2half2_rn(acc[mt][nt][2], acc[mt][nt][3]);
            *(__half2*)&hsm[row * 264 + col] = h0;
            *(__half2*)&hsm[(row + 8) * 264 + col] = h1;
        }
    }
    __syncthreads();
#pragma unroll
    for (int p = 0; p < 8; p++) {
        int idx = tid + p * 512;
        int row = idx >> 5, c16 = idx & 31;
        uint4 v = *(uint4*)&hsm[row * 264 + c16 * 8];
        *(uint4*)(Ch + (size_t)(m0 + row) * NTOT + n0 + c16 * 8) = v;
    }
}

// ---------------- 512-thread generic hgemm (128x256 tile) -------------------
template <int NTOT, int K, int WF32, int H16, int EPI>
__global__ __launch_bounds__(512, 1)
void hgemm512(const __half* __restrict__ A, const __half* __restrict__ W,
              float* __restrict__ C, __half* __restrict__ Ch,
              const float* __restrict__ bias, const float* __restrict__ res) {
    extern __shared__ __half hsm[];
    const int tid = threadIdx.x;
    const int m0 = blockIdx.y * 128, n0 = blockIdx.x * 256;
    const int lane = tid & 31, wid = tid >> 5;
    const int wm0 = (wid >> 3) * 64;
    const int wn0 = (wid & 7) * 32;
    const int g = lane >> 2, tq = lane & 3;
    const uint32_t sb = smem_u32(hsm);

    float acc[4][4][4];
#pragma unroll
    for (int i = 0; i < 4; i++)
#pragma unroll
        for (int j = 0; j < 4; j++)
#pragma unroll
            for (int c = 0; c < 4; c++) acc[i][j][c] = 0.f;

    const int am  = tid >> 2;
    const int akg = tid & 3;
    const int bk  = tid >> 5;
    const int bg  = tid & 31;
    const __half* aptr = A + (size_t)(m0 + am) * K + akg * 8;
    const __half* wptr = W + (size_t)bk * NTOT + n0 + bg * 8;
    const uint32_t adst = sb + (uint32_t)(am * 40 + akg * 8) * 2;
    const uint32_t bdst = sb + (uint32_t)(20480 + bk * 264 + bg * 8) * 2;

    const int NT = K / 32;
#pragma unroll 1
    for (int p = 0; p < 3; p++) {
        cpa16(adst + (uint32_t)(p * 5120) * 2, aptr + (size_t)p * 32);
        uint32_t bd = bdst + (uint32_t)(p * 8448) * 2;
        const __half* wp = wptr + (size_t)p * 32 * NTOT;
        cpa16(bd, wp);
        cpa16(bd + (uint32_t)(16 * 264) * 2, wp + (size_t)16 * NTOT);
        CP_COMMIT();
    }

    const int a_r = lane & 15;
    const int a_c = (lane >> 4) * 8;

#pragma unroll 1
    for (int t0 = 0; t0 < NT; t0 += 4) {
#pragma unroll
        for (int tt = 0; tt < 4; tt++) {
            const int t = t0 + tt;
            CP_WAIT2();
            __syncthreads();
            if (t + 3 < NT) {
                const int sn = (tt + 3) & 3;
                cpa16(adst + (uint32_t)(sn * 5120) * 2, aptr + (size_t)(t + 3) * 32);
                uint32_t bd = bdst + (uint32_t)(sn * 8448) * 2;
                const __half* wp = wptr + (size_t)(t + 3) * 32 * NTOT;
                cpa16(bd, wp);
                cpa16(bd + (uint32_t)(16 * 264) * 2, wp + (size_t)16 * NTOT);
            }
            CP_COMMIT();
            const int s = tt;
            const uint32_t as_ = sb + (uint32_t)(s * 5120) * 2;
            const uint32_t bs_ = sb + (uint32_t)(20480 + s * 8448) * 2;
#pragma unroll
            for (int ks = 0; ks < 2; ks++) {
                unsigned af[4][4], bf[4][2];
#pragma unroll
                for (int mt = 0; mt < 4; mt++)
                    ldsm4(af[mt][0], af[mt][1], af[mt][2], af[mt][3],
                          as_ + (uint32_t)((wm0 + mt * 16 + a_r) * 40 + ks * 16 + a_c) * 2);
#pragma unroll
                for (int nq = 0; nq < 2; nq++)
                    ldsm4t(bf[2 * nq][0], bf[2 * nq][1], bf[2 * nq + 1][0], bf[2 * nq + 1][1],
                           bs_ + (uint32_t)((ks * 16 + a_r) * 264 + wn0 + nq * 16 + a_c) * 2);
#pragma unroll
                for (int mt = 0; mt < 4; mt++)
#pragma unroll
                    for (int nt = 0; nt < 4; nt++)
                        mma_f16(acc[mt][nt], af[mt], bf[nt]);
            }
        }
    }

    if (H16) {
        // ---- smem-staged fp16 store (128B-coalesced) ----
        __syncthreads();
#pragma unroll
        for (int mt = 0; mt < 4; mt++) {
            int row = wm0 + mt * 16 + g;
#pragma unroll
            for (int nt = 0; nt < 4; nt++) {
                int col = wn0 + nt * 8 + 2 * tq;
                int cb = n0 + col;
                float2 bv = *(const float2*)(bias + cb);
                float v0 = acc[mt][nt][0] + bv.x;
                float v1 = acc[mt][nt][1] + bv.y;
                float v2 = acc[mt][nt][2] + bv.x;
                float v3 = acc[mt][nt][3] + bv.y;
                if (EPI == EPI_GELU) {
                    v0 *= normcdff(v0); v1 *= normcdff(v1);
                    v2 *= normcdff(v2); v3 *= normcdff(v3);
                }
                __half2 h0 = __floats2half2_rn(v0, v1);
                __half2 h1 = __floats2half2_rn(v2, v3);
                *(__half2*)&hsm[row * 264 + col] = h0;
                *(__half2*)&hsm[(row + 8) * 264 + col] = h1;
            }
        }
        __syncthreads();
#pragma unroll
        for (int p = 0; p < 8; p++) {
            int idx = tid + p * 512;
            int row = idx >> 5, c16 = idx & 31;
            uint4 v = *(uint4*)&hsm[row * 264 + c16 * 8];
            *(uint4*)(Ch + (size_t)(m0 + row) * NTOT + n0 + c16 * 8) = v;
        }
        return;
    }

#pragma unroll
    for (int mt = 0; mt < 4; mt++) {
        int r0 = m0 + wm0 + mt * 16 + g;
#pragma unroll
        for (int nt = 0; nt < 4; nt++) {
            int cb = n0 + wn0 + nt * 8 + 2 * tq;
            float2 bv = *(const float2*)(bias + cb);
            float v0 = acc[mt][nt][0] + bv.x;
            float v1 = acc[mt][nt][1] + bv.y;
            float v2 = acc[mt][nt][2] + bv.x;
            float v3 = acc[mt][nt][3] + bv.y;
            if (EPI == EPI_GELU) {
                v0 *= normcdff(v0); v1 *= normcdff(v1);
                v2 *= normcdff(v2); v3 *= normcdff(v3);
            }
            size_t o0 = (size_t)r0 * NTOT + cb;
            size_t o1 = (size_t)(r0 + 8) * NTOT + cb;
            if (EPI == EPI_RES) {
                float2 r0v = *(const float2*)(res + o0);
                float2 r1v = *(const float2*)(res + o1);
                v0 += r0v.x; v1 += r0v.y; v2 += r1v.x; v3 += r1v.y;
            }
            if (WF32) {
                float2 s0 = {v0, v1}, s1 = {v2, v3};
                *(float2*)(C + o0) = s0;
                *(float2*)(C + o1) = s1;
            }
        }
    }
}

// ---------------- context partials via mma: ctxp = k^T v ----------------
__global__ __launch_bounds__(256, 2)
void ctx_mma(const __half* __restrict__ qkvh, float* __restrict__ ctxp) {
    __shared__ __half Kt[32][136];
    __shared__ __half Vt[32][136];
    const int bh = blockIdx.x, split = blockIdx.y;
    const int b = bh >> 2, h = bh & 3;
    const int tid = threadIdx.x, lane = tid & 31, wid = tid >> 5;
    const int wm0 = (wid >> 2) * 64, wn0 = (wid & 3) * 32;
    const int g = lane >> 2, tq = lane & 3;
    const uint32_t kb = smem_u32(Kt), vb = smem_u32(Vt);

    float acc[4][4][4];
#pragma unroll
    for (int i = 0; i < 4; i++)
#pragma unroll
        for (int j = 0; j < 4; j++)
#pragma unroll
            for (int c = 0; c < 4; c++) acc[i][j][c] = 0.f;

    const int arA = lane & 7, acA = (lane >> 3) & 1, asA = (lane >> 4) & 1;
    const int a_r = lane & 15, a_c = (lane >> 4) * 8;

    for (int ch = 0; ch < (NN / CSPLIT) / 32; ch++) {
        int nb = split * (NN / CSPLIT) + ch * 32;
        if (ch) __syncthreads();
#pragma unroll
        for (int i = 0; i < 2; i++) {
            int idx = tid + i * 256;
            int row = idx >> 4, gc = idx & 15;
            size_t src = ((size_t)(b * NN + nb + row)) * 1536 + (size_t)h * DD + gc * 8;
            *(uint4*)&Kt[row][gc * 8] = *(const uint4*)(qkvh + src + 512);
            *(uint4*)&Vt[row][gc * 8] = *(const uint4*)(qkvh + src + 1024);
        }
        __syncthreads();
#pragma unroll
        for (int ks = 0; ks < 2; ks++) {
            unsigned af[4][4], bf[4][2];
#pragma unroll
            for (int mt = 0; mt < 4; mt++)
                ldsm4t(af[mt][0], af[mt][1], af[mt][2], af[mt][3],
                       kb + (uint32_t)((ks * 16 + arA + asA * 8) * 136 +
                                       wm0 + mt * 16 + acA * 8) * 2);
#pragma unroll
            for (int nq = 0; nq < 2; nq++)
                ldsm4t(bf[2 * nq][0], bf[2 * nq][1], bf[2 * nq + 1][0], bf[2 * nq + 1][1],
                       vb + (uint32_t)((ks * 16 + a_r) * 136 + wn0 + nq * 16 + a_c) * 2);
#pragma unroll
            for (int mt = 0; mt < 4; mt++)
#pragma unroll
                for (int nt = 0; nt < 4; nt++)
                    mma_f16(acc[mt][nt], af[mt], bf[nt]);
        }
    }
    float* outp = ctxp + ((size_t)split * 16 + bh) * (DD * DD);
#pragma unroll
    for (int mt = 0; mt < 4; mt++) {
        int d = wm0 + mt * 16 + g;
#pragma unroll
        for (int nt = 0; nt < 4; nt++) {
            int e = wn0 + nt * 8 + 2 * tq;
            float2 s0 = {acc[mt][nt][0], acc[mt][nt][1]};
            float2 s1 = {acc[mt][nt][2], acc[mt][nt][3]};
            *(float2*)(outp + (size_t)d * DD + e) = s0;
            *(float2*)(outp + (size_t)(d + 8) * DD + e) = s1;
        }
    }
}

__global__ void reduce_ctx(const float* __restrict__ ctxp, __half* __restrict__ ctxh) {
    int i = blockIdx.x * blockDim.x + threadIdx.x;
    float s = 0.f;
#pragma unroll
    for (int sp = 0; sp < CSPLIT; sp++) s += ctxp[(size_t)sp * (16 * DD * DD) + i];
    ctxh[i] = __float2half(s * SCALE);
}

// ---------------- attn = q @ (ctx*scale) via mma, fp16 out ----------------
#define ASM_BYTES (2 * 128 * 136 * 2)
__global__ __launch_bounds__(256, 2)
void attn_mma(const __half* __restrict__ qkvh, const __half* __restrict__ ctxh,
              __half* __restrict__ attnh) {
    extern __shared__ __half asmem[];
    __half* Qs = asmem;
    __half* Cs = asmem + 128 * 136;
    const int tile = blockIdx.x, bh = blockIdx.y;
    const int b = bh >> 2, h = bh & 3;
    const int tid = threadIdx.x, lane = tid & 31, wid = tid >> 5;
    const int wm0 = (wid >> 2) * 64, wn0 = (wid & 3) * 32;
    const int g = lane >> 2, tq = lane & 3;

#pragma unroll
    for (int i = 0; i < 8; i++) {
        int idx = tid + i * 256;
        int row = idx >> 4, gc = idx & 15;
        *(uint4*)&Qs[row * 136 + gc * 8] =
            *(const uint4*)(qkvh + ((size_t)(b * NN + tile * 128 + row)) * 1536 +
                            (size_t)h * DD + gc * 8);
        *(uint4*)&Cs[row * 136 + gc * 8] =
            *(const uint4*)(ctxh + (size_t)bh * (DD * DD) + (size_t)row * DD + gc * 8);
    }
    __syncthreads();

    float acc[4][4][4];
#pragma unroll
    for (int i = 0; i < 4; i++)
#pragma unroll
        for (int j = 0; j < 4; j++)
#pragma unroll
            for (int c = 0; c < 4; c++) acc[i][j][c] = 0.f;

    const uint32_t qb = smem_u32(Qs), cb2 = smem_u32(Cs);
    const int a_r = lane & 15, a_c = (lane >> 4) * 8;

#pragma unroll
    for (int ks = 0; ks < 8; ks++) {
        unsigned af[4][4], bf[4][2];
#pragma unroll
        for (int mt = 0; mt < 4; mt++)
            ldsm4(af[mt][0], af[mt][1], af[mt][2], af[mt][3],
                  qb + (uint32_t)((wm0 + mt * 16 + a_r) * 136 + ks * 16 + a_c) * 2);
#pragma unroll
        for (int nq = 0; nq < 2; nq++)
            ldsm4t(bf[2 * nq][0], bf[2 * nq][1], bf[2 * nq + 1][0], bf[2 * nq + 1][1],
                   cb2 + (uint32_t)((ks * 16 + a_r) * 136 + wn0 + nq * 16 + a_c) * 2);
#pragma unroll
        for (int mt = 0; mt < 4; mt++)
#pragma unroll
            for (int nt = 0; nt < 4; nt++)
                mma_f16(acc[mt][nt], af[mt], bf[nt]);
    }

    // ---- smem-staged fp16 store (reuse Qs region) ----
    __syncthreads();
#pragma unroll
    for (int mt = 0; mt < 4; mt++) {
        int row = wm0 + mt * 16 + g;
#pragma unroll
        for (int nt = 0; nt < 4; nt++) {
            int col = wn0 + nt * 8 + 2 * tq;
            __half2 h0 = __floats2half2_rn(acc[mt][nt][0], acc[mt][nt][1]);
            __half2 h1 = __floats2half2_rn(acc[mt][nt][2], acc[mt][nt][3]);
            *(__half2*)&Qs[row * 136 + col] = h0;
            *(__half2*)&Qs[(row + 8) * 136 + col] = h1;
        }
    }
    __syncthreads();
#pragma unroll
    for (int p = 0; p < 8; p++) {
        int idx = tid + p * 256;
        int row = idx >> 4, c16 = idx & 15;
        uint4 v = *(uint4*)&Qs[row * 136 + c16 * 8];
        *(uint4*)(attnh + (size_t)(b * NN + tile * 128 + row) * CC + h * DD + c16 * 8) = v;
    }
}

// ---------------- launch ----------------
extern "C" void kernel_launch(void* const* d_in, const int* in_sizes, int n_in,
                              void* d_out, int out_size) {
    const float* x       = (const float*)d_in[0];
    const float* norm1_w = (const float*)d_in[1];
    const float* norm1_b = (const float*)d_in[2];
    const float* qkv_w   = (const float*)d_in[3];
    const float* qkv_b   = (const float*)d_in[4];
    const float* lnk_w   = (const float*)d_in[5];
    const float* lnk_b   = (const float*)d_in[6];
    const float* lnv_w   = (const float*)d_in[7];
    const float* lnv_b   = (const float*)d_in[8];
    const float* proj_w  = (const float*)d_in[9];
    const float* proj_b  = (const float*)d_in[10];
    const float* norm2_w = (const float*)d_in[11];
    const float* norm2_b = (const float*)d_in[12];
    const float* mlp_w1  = (const float*)d_in[13];
    const float* mlp_b1  = (const float*)d_in[14];
    const float* mlp_w2  = (const float*)d_in[15];
    const float* mlp_b2  = (const float*)d_in[16];
    float* out = (float*)d_out;

    float  *x1, *ctxp;
    __half *xh, *qkvh, *attnh, *mlphh, *ctxh, *wh;
    cudaGetSymbolAddress((void**)&x1,    g_x1);
    cudaGetSymbolAddress((void**)&ctxp,  g_ctxp);
    cudaGetSymbolAddress((void**)&xh,    g_xh);
    cudaGetSymbolAddress((void**)&qkvh,  g_qkvh);
    cudaGetSymbolAddress((void**)&attnh, g_attnh);
    cudaGetSymbolAddress((void**)&mlphh, g_mlphh);
    cudaGetSymbolAddress((void**)&ctxh,  g_ctxh);
    cudaGetSymbolAddress((void**)&wh,    g_wh);

    cudaFuncSetAttribute(qkv512,
                         cudaFuncAttributeMaxDynamicSharedMemorySize, HSM_BYTES);
    cudaFuncSetAttribute(hgemm512<512, 512, 1, 0, EPI_RES>,
                         cudaFuncAttributeMaxDynamicSharedMemorySize, HSM_BYTES);
    cudaFuncSetAttribute(hgemm512<2048, 512, 0, 1, EPI_GELU>,
                         cudaFuncAttributeMaxDynamicSharedMemorySize, HSM_BYTES);
    cudaFuncSetAttribute(hgemm512<512, 2048, 1, 0, EPI_RES>,
                         cudaFuncAttributeMaxDynamicSharedMemorySize, HSM_BYTES);
    cudaFuncSetAttribute(attn_mma,
                         cudaFuncAttributeMaxDynamicSharedMemorySize, ASM_BYTES);

    // 0. all weights -> fp16 (one launch)
    f2h_all<<<3072, 256>>>(qkv_w, proj_w, mlp_w1, mlp_w2, wh);

    // 1. LN1 -> fp16
    ln_rows512<<<MTOK, 256>>>(x, xh, norm1_w, norm1_b);
    // 2. qkv = xn @ qkv_w + b, fused k/v LN, fp16 out
    qkv512<<<dim3(6, 256), 512, HSM_BYTES>>>(
        xh, wh + WH_QKV, qkvh, qkv_b, lnk_w, lnk_b, lnv_w, lnv_b);
    // 3. context = k^T v ; reduce * SCALE -> fp16
    ctx_mma<<<dim3(16, CSPLIT), 256>>>(qkvh, ctxp);
    reduce_ctx<<<1024, 256>>>(ctxp, ctxh);
    // 4. attn = q @ ctx -> fp16
    attn_mma<<<dim3(64, 16), 256, ASM_BYTES>>>(qkvh, ctxh, attnh);
    // 5. x1 = x + attn @ proj_w + b  (fp32)
    hgemm512<512, 512, 1, 0, EPI_RES><<<dim3(2, 256), 512, HSM_BYTES>>>(
        attnh, wh + WH_PROJ, x1, nullptr, proj_b, x);
    // 6. LN2 -> fp16
    ln_rows512<<<MTOK, 256>>>(x1, xh, norm2_w, norm2_b);
    // 7. mlp hidden = gelu(h @ w1 + b1)  (fp16 only)
    hgemm512<2048, 512, 0, 1, EPI_GELU><<<dim3(8, 256), 512, HSM_BYTES>>>(
        xh, wh + WH_MLP1, nullptr, mlphh, mlp_b1, nullptr);
    // 8. out = x1 + mlph @ w2 + b2  (fp32)
    hgemm512<512, 2048, 1, 0, EPI_RES><<<dim3(2, 256), 512, HSM_BYTES>>>(
        mlphh, wh + WH_MLP2, out, nullptr, mlp_b2, x1);
}

// round 16
// speedup vs baseline: 1.1945x; 1.0076x over previous
#include <cuda_runtime.h>
#include <cuda_fp16.h>
#include <cstdint>

// ---------------- problem constants ----------------
#define BB 4
#define NN 8192
#define CC 512
#define DD 128
#define HID 2048
#define MTOK 32768
#define EPS 1e-5f
#define SCALE 0.08838834764831845f   // 128^-0.5
#define CSPLIT 16

// ---------------- scratch ----------------
__device__ float  g_x1  [(size_t)MTOK * CC];          // fp32 residual
__device__ float  g_ctxp[(size_t)CSPLIT * 16 * DD * DD];
__device__ __half g_xh   [(size_t)MTOK * CC];         // LN1/LN2 out (fp16)
__device__ __half g_qkvh [(size_t)MTOK * 1536];       // fp16 q + LN'd k,v
__device__ __half g_attnh[(size_t)MTOK * CC];
__device__ __half g_mlphh[(size_t)MTOK * HID];
__device__ __half g_ctxh [(size_t)16 * DD * DD];
__device__ __half g_wh   [(size_t)3145728];           // all weights fp16

#define WH_QKV  0
#define WH_PROJ 786432
#define WH_MLP1 1048576
#define WH_MLP2 2097152

// ---------------- ptx helpers ----------------
__device__ __forceinline__ uint32_t smem_u32(const void* p) {
    uint32_t r;
    asm("{ .reg .u64 t; cvta.to.shared.u64 t, %1; cvt.u32.u64 %0, t; }" : "=r"(r) : "l"(p));
    return r;
}
__device__ __forceinline__ void mma_f16(float* d, const unsigned* a, const unsigned* b) {
    asm volatile(
        "mma.sync.aligned.m16n8k16.row.col.f32.f16.f16.f32 "
        "{%0,%1,%2,%3}, {%4,%5,%6,%7}, {%8,%9}, {%0,%1,%2,%3};"
        : "+f"(d[0]), "+f"(d[1]), "+f"(d[2]), "+f"(d[3])
        : "r"(a[0]), "r"(a[1]), "r"(a[2]), "r"(a[3]), "r"(b[0]), "r"(b[1]));
}
__device__ __forceinline__ void ldsm4(unsigned& r0, unsigned& r1, unsigned& r2, unsigned& r3, uint32_t a) {
    asm volatile("ldmatrix.sync.aligned.m8n8.x4.shared.b16 {%0,%1,%2,%3}, [%4];"
                 : "=r"(r0), "=r"(r1), "=r"(r2), "=r"(r3) : "r"(a));
}
__device__ __forceinline__ void ldsm4t(unsigned& r0, unsigned& r1, unsigned& r2, unsigned& r3, uint32_t a) {
    asm volatile("ldmatrix.sync.aligned.m8n8.x4.trans.shared.b16 {%0,%1,%2,%3}, [%4];"
                 : "=r"(r0), "=r"(r1), "=r"(r2), "=r"(r3) : "r"(a));
}
__device__ __forceinline__ void cpa16(uint32_t dst, const void* src) {
    asm volatile("cp.async.cg.shared.global [%0], [%1], 16;" :: "r"(dst), "l"(src));
}
#define CP_COMMIT() asm volatile("cp.async.commit_group;" ::: "memory")
#define CP_WAIT2()  asm volatile("cp.async.wait_group 2;" ::: "memory")
#define CP_WAIT0()  asm volatile("cp.async.wait_group 0;" ::: "memory")

// ---------------- fused fp32 -> fp16 weight convert ----------------
__global__ void f2h_all(const float* __restrict__ a, const float* __restrict__ b,
                        const float* __restrict__ c, const float* __restrict__ d,
                        __half* __restrict__ out) {
    int i = (blockIdx.x * 256 + threadIdx.x) * 4;
    const float* src; int off;
    if (i < 786432)       { src = a; off = i; }
    else if (i < 1048576) { src = b; off = i - 786432; }
    else if (i < 2097152) { src = c; off = i - 1048576; }
    else                  { src = d; off = i - 2097152; }
    float4 v = *(const float4*)(src + off);
    __half2 h0 = __floats2half2_rn(v.x, v.y), h1 = __floats2half2_rn(v.z, v.w);
    uint2 u; u.x = *(unsigned*)&h0; u.y = *(unsigned*)&h1;
    *(uint2*)(out + i) = u;
}

// ---------------- LayerNorm over 512 (fp32 in, fp16 out) ----------------
__global__ void ln_rows512(const float* __restrict__ x, __half* __restrict__ y,
                           const float* __restrict__ w, const float* __restrict__ b) {
    int row = blockIdx.x;
    const float* xr = x + (size_t)row * CC;
    int t = threadIdx.x;
    float2 v = *(const float2*)(xr + 2 * t);
    float s = v.x + v.y, s2 = v.x * v.x + v.y * v.y;
#pragma unroll
    for (int o = 16; o > 0; o >>= 1) {
        s  += __shfl_xor_sync(0xffffffffu, s,  o);
        s2 += __shfl_xor_sync(0xffffffffu, s2, o);
    }
    __shared__ float sh[18];
    int wid = t >> 5, lane = t & 31;
    if (lane == 0) { sh[wid] = s; sh[wid + 8] = s2; }
    __syncthreads();
    if (t == 0) {
        float ts = 0.f, ts2 = 0.f;
#pragma unroll
        for (int i = 0; i < 8; i++) { ts += sh[i]; ts2 += sh[i + 8]; }
        float mu  = ts * (1.f / CC);
        float var = ts2 * (1.f / CC) - mu * mu;
        sh[16] = mu; sh[17] = rsqrtf(var + EPS);
    }
    __syncthreads();
    float mu = sh[16], inv = sh[17];
    float2 wv = *(const float2*)(w + 2 * t);
    float2 bv = *(const float2*)(b + 2 * t);
    __half2 o = __floats2half2_rn((v.x - mu) * inv * wv.x + bv.x,
                                  (v.y - mu) * inv * wv.y + bv.y);
    *(__half2*)(y + (size_t)row * CC + 2 * t) = o;
}

// ---------------- 512-thread GEMM mainloop ----------------
#define EPI_GELU 1
#define EPI_RES  2
#define HSM_BYTES ((4*128*40 + 4*32*264) * 2)

// ---------------- qkv GEMM, 512 threads, fused k/v LN epilogue --------------
__global__ __launch_bounds__(512, 1)
void qkv512(const __half* __restrict__ A, const __half* __restrict__ W,
            __half* __restrict__ Ch, const float* __restrict__ bias,
            const float* __restrict__ lnk_w, const float* __restrict__ lnk_b,
            const float* __restrict__ lnv_w, const float* __restrict__ lnv_b) {
    extern __shared__ __half hsm[];
    const int NTOT = 1536, K = 512;
    const int tid = threadIdx.x;
    const int m0 = blockIdx.y * 128, n0 = blockIdx.x * 256;
    const int lane = tid & 31, wid = tid >> 5;
    const int wm0 = (wid >> 3) * 64;
    const int wn0 = (wid & 7) * 32;
    const int g = lane >> 2, tq = lane & 3;
    const uint32_t sb = smem_u32(hsm);

    float acc[4][4][4];
#pragma unroll
    for (int i = 0; i < 4; i++)
#pragma unroll
        for (int j = 0; j < 4; j++)
#pragma unroll
            for (int c = 0; c < 4; c++) acc[i][j][c] = 0.f;

    const int am  = tid >> 2;
    const int akg = tid & 3;
    const int bk  = tid >> 5;
    const int bg  = tid & 31;
    const __half* aptr = A + (size_t)(m0 + am) * K + akg * 8;
    const __half* wptr = W + (size_t)bk * NTOT + n0 + bg * 8;
    const uint32_t adst = sb + (uint32_t)(am * 40 + akg * 8) * 2;
    const uint32_t bdst = sb + (uint32_t)(20480 + bk * 264 + bg * 8) * 2;

    const int NT = K / 32;
#pragma unroll 1
    for (int p = 0; p < 3; p++) {
        cpa16(adst + (uint32_t)(p * 5120) * 2, aptr + (size_t)p * 32);
        uint32_t bd = bdst + (uint32_t)(p * 8448) * 2;
        const __half* wp = wptr + (size_t)p * 32 * NTOT;
        cpa16(bd, wp);
        cpa16(bd + (uint32_t)(16 * 264) * 2, wp + (size_t)16 * NTOT);
        CP_COMMIT();
    }

    const int a_r = lane & 15;
    const int a_c = (lane >> 4) * 8;

#pragma unroll 1
    for (int t0 = 0; t0 < NT; t0 += 4) {
#pragma unroll
        for (int tt = 0; tt < 4; tt++) {
            const int t = t0 + tt;
            CP_WAIT2();
            __syncthreads();
            if (t + 3 < NT) {
                const int sn = (tt + 3) & 3;
                cpa16(adst + (uint32_t)(sn * 5120) * 2, aptr + (size_t)(t + 3) * 32);
                uint32_t bd = bdst + (uint32_t)(sn * 8448) * 2;
                const __half* wp = wptr + (size_t)(t + 3) * 32 * NTOT;
                cpa16(bd, wp);
                cpa16(bd + (uint32_t)(16 * 264) * 2, wp + (size_t)16 * NTOT);
            }
            CP_COMMIT();
            const int s = tt;
            const uint32_t as_ = sb + (uint32_t)(s * 5120) * 2;
            const uint32_t bs_ = sb + (uint32_t)(20480 + s * 8448) * 2;
#pragma unroll
            for (int ks = 0; ks < 2; ks++) {
                unsigned af[4][4], bf[4][2];
#pragma unroll
                for (int mt = 0; mt < 4; mt++)
                    ldsm4(af[mt][0], af[mt][1], af[mt][2], af[mt][3],
                          as_ + (uint32_t)((wm0 + mt * 16 + a_r) * 40 + ks * 16 + a_c) * 2);
#pragma unroll
                for (int nq = 0; nq < 2; nq++)
                    ldsm4t(bf[2 * nq][0], bf[2 * nq][1], bf[2 * nq + 1][0], bf[2 * nq + 1][1],
                           bs_ + (uint32_t)((ks * 16 + a_r) * 264 + wn0 + nq * 16 + a_c) * 2);
#pragma unroll
                for (int mt = 0; mt < 4; mt++)
#pragma unroll
                    for (int nt = 0; nt < 4; nt++)
                        mma_f16(acc[mt][nt], af[mt], bf[nt]);
            }
        }
    }

    // ---- bias ----
#pragma unroll
    for (int mt = 0; mt < 4; mt++)
#pragma unroll
        for (int nt = 0; nt < 4; nt++) {
            int cb = n0 + wn0 + nt * 8 + 2 * tq;
            float2 bv = *(const float2*)(bias + cb);
            acc[mt][nt][0] += bv.x; acc[mt][nt][1] += bv.y;
            acc[mt][nt][2] += bv.x; acc[mt][nt][3] += bv.y;
        }

    // ---- fused per-head LN for k (x∈{2,3}) / v (x∈{4,5}) ----
    if (blockIdx.x >= 2) {
        const float* lw = (blockIdx.x < 4) ? lnk_w : lnv_w;
        const float* lb = (blockIdx.x < 4) ? lnk_b : lnv_b;
        float* red = (float*)hsm;        // [2 heads][128 rows][4 nwarps][2] = 8KB
        const int head = (wid >> 2) & 1;
        const int j = wid & 3;
        float ps[4][2], ps2[4][2];
#pragma unroll
        for (int mt = 0; mt < 4; mt++)
#pragma unroll
            for (int h2 = 0; h2 < 2; h2++) {
                float s = 0.f, s2 = 0.f;
#pragma unroll
                for (int nt = 0; nt < 4; nt++) {
                    float a = acc[mt][nt][2 * h2], b = acc[mt][nt][2 * h2 + 1];
                    s += a + b; s2 += a * a + b * b;
                }
                ps[mt][h2] = s; ps2[mt][h2] = s2;
            }
#pragma unroll
        for (int off = 1; off < 4; off <<= 1)
#pragma unroll
            for (int mt = 0; mt < 4; mt++)
#pragma unroll
                for (int h2 = 0; h2 < 2; h2++) {
                    ps[mt][h2]  += __shfl_xor_sync(0xffffffffu, ps[mt][h2],  off);
                    ps2[mt][h2] += __shfl_xor_sync(0xffffffffu, ps2[mt][h2], off);
                }
        __syncthreads();
        if (tq == 0) {
#pragma unroll
            for (int mt = 0; mt < 4; mt++)
#pragma unroll
                for (int h2 = 0; h2 < 2; h2++) {
                    int row = wm0 + mt * 16 + g + 8 * h2;
                    int idx = ((head * 128 + row) * 4 + j) * 2;
                    red[idx] = ps[mt][h2]; red[idx + 1] = ps2[mt][h2];
                }
        }
        __syncthreads();
#pragma unroll
        for (int mt = 0; mt < 4; mt++) {
            float mu[2], inv[2];
#pragma unroll
            for (int h2 = 0; h2 < 2; h2++) {
                int row = wm0 + mt * 16 + g + 8 * h2;
                int i0 = (head * 128 + row) * 8;
                float s  = red[i0] + red[i0 + 2] + red[i0 + 4] + red[i0 + 6];
                float s2 = red[i0 + 1] + red[i0 + 3] + red[i0 + 5] + red[i0 + 7];
                float m = s * (1.f / 128);
                mu[h2] = m;
                inv[h2] = rsqrtf(s2 * (1.f / 128) - m * m + EPS);
            }
#pragma unroll
            for (int nt = 0; nt < 4; nt++) {
                int ch = j * 32 + nt * 8 + 2 * tq;
                float2 lwv = *(const float2*)(lw + ch);
                float2 lbv = *(const float2*)(lb + ch);
                acc[mt][nt][0] = (acc[mt][nt][0] - mu[0]) * inv[0] * lwv.x + lbv.x;
                acc[mt][nt][1] = (acc[mt][nt][1] - mu[0]) * inv[0] * lwv.y + lbv.y;
                acc[mt][nt][2] = (acc[mt][nt][2] - mu[1]) * inv[1] * lwv.x + lbv.x;
                acc[mt][nt][3] = (acc[mt][nt][3] - mu[1]) * inv[1] * lwv.y + lbv.y;
            }
        }
    }

    // ---- smem-staged fp16 store (128B-coalesced) ----
    __syncthreads();                 // pipeline smem + LN red reads done
#pragma unroll
    for (int mt = 0; mt < 4; mt++) {
        int row = wm0 + mt * 16 + g;
#pragma unroll
        for (int nt = 0; nt < 4; nt++) {
            int col = wn0 + nt * 8 + 2 * tq;
            __half2 h0 = __floats2half2_rn(acc[mt][nt][0], acc[mt][nt][1]);
            __half2 h1 = __floats2half2_rn(acc[mt][nt][2], acc[mt][nt][3]);
            *(__half2*)&hsm[row * 264 + col] = h0;
            *(__half2*)&hsm[(row + 8) * 264 + col] = h1;
        }
    }
    __syncthreads();
#pragma unroll
    for (int p = 0; p < 8; p++) {
        int idx = tid + p * 512;
        int row = idx >> 5, c16 = idx & 31;
        uint4 v = *(uint4*)&hsm[row * 264 + c16 * 8];
        *(uint4*)(Ch + (size_t)(m0 + row) * NTOT + n0 + c16 * 8) = v;
    }
}

// ---------------- 512-thread generic hgemm (128x256 tile) -------------------
template <int NTOT, int K, int WF32, int H16, int EPI>
__global__ __launch_bounds__(512, 1)
void hgemm512(const __half* __restrict__ A, const __half* __restrict__ W,
              float* __restrict__ C, __half* __restrict__ Ch,
              const float* __restrict__ bias, const float* __restrict__ res) {
    extern __shared__ __half hsm[];
    const int tid = threadIdx.x;
    const int m0 = blockIdx.y * 128, n0 = blockIdx.x * 256;
    const int lane = tid & 31, wid = tid >> 5;
    const int wm0 = (wid >> 3) * 64;
    const int wn0 = (wid & 7) * 32;
    const int g = lane >> 2, tq = lane & 3;
    const uint32_t sb = smem_u32(hsm);

    float acc[4][4][4];
#pragma unroll
    for (int i = 0; i < 4; i++)
#pragma unroll
        for (int j = 0; j < 4; j++)
#pragma unroll
            for (int c = 0; c < 4; c++) acc[i][j][c] = 0.f;

    const int am  = tid >> 2;
    const int akg = tid & 3;
    const int bk  = tid >> 5;
    const int bg  = tid & 31;
    const __half* aptr = A + (size_t)(m0 + am) * K + akg * 8;
    const __half* wptr = W + (size_t)bk * NTOT + n0 + bg * 8;
    const uint32_t adst = sb + (uint32_t)(am * 40 + akg * 8) * 2;
    const uint32_t bdst = sb + (uint32_t)(20480 + bk * 264 + bg * 8) * 2;

    const int NT = K / 32;
#pragma unroll 1
    for (int p = 0; p < 3; p++) {
        cpa16(adst + (uint32_t)(p * 5120) * 2, aptr + (size_t)p * 32);
        uint32_t bd = bdst + (uint32_t)(p * 8448) * 2;
        const __half* wp = wptr + (size_t)p * 32 * NTOT;
        cpa16(bd, wp);
        cpa16(bd + (uint32_t)(16 * 264) * 2, wp + (size_t)16 * NTOT);
        CP_COMMIT();
    }

    const int a_r = lane & 15;
    const int a_c = (lane >> 4) * 8;

#pragma unroll 1
    for (int t0 = 0; t0 < NT; t0 += 4) {
#pragma unroll
        for (int tt = 0; tt < 4; tt++) {
            const int t = t0 + tt;
            CP_WAIT2();
            __syncthreads();
            if (t + 3 < NT) {
                const int sn = (tt + 3) & 3;
                cpa16(adst + (uint32_t)(sn * 5120) * 2, aptr + (size_t)(t + 3) * 32);
                uint32_t bd = bdst + (uint32_t)(sn * 8448) * 2;
                const __half* wp = wptr + (size_t)(t + 3) * 32 * NTOT;
                cpa16(bd, wp);
                cpa16(bd + (uint32_t)(16 * 264) * 2, wp + (size_t)16 * NTOT);
            }
            CP_COMMIT();
            const int s = tt;
            const uint32_t as_ = sb + (uint32_t)(s * 5120) * 2;
            const uint32_t bs_ = sb + (uint32_t)(20480 + s * 8448) * 2;
#pragma unroll
            for (int ks = 0; ks < 2; ks++) {
                unsigned af[4][4], bf[4][2];
#pragma unroll
                for (int mt = 0; mt < 4; mt++)
                    ldsm4(af[mt][0], af[mt][1], af[mt][2], af[mt][3],
                          as_ + (uint32_t)((wm0 + mt * 16 + a_r) * 40 + ks * 16 + a_c) * 2);
#pragma unroll
                for (int nq = 0; nq < 2; nq++)
                    ldsm4t(bf[2 * nq][0], bf[2 * nq][1], bf[2 * nq + 1][0], bf[2 * nq + 1][1],
                           bs_ + (uint32_t)((ks * 16 + a_r) * 264 + wn0 + nq * 16 + a_c) * 2);
#pragma unroll
                for (int mt = 0; mt < 4; mt++)
#pragma unroll
                    for (int nt = 0; nt < 4; nt++)
                        mma_f16(acc[mt][nt], af[mt], bf[nt]);
            }
        }
    }

    if (H16) {
        // ---- smem-staged fp16 store (128B-coalesced) ----
        __syncthreads();
#pragma unroll
        for (int mt = 0; mt < 4; mt++) {
            int row = wm0 + mt * 16 + g;
#pragma unroll
            for (int nt = 0; nt < 4; nt++) {
                int col = wn0 + nt * 8 + 2 * tq;
                int cb = n0 + col;
                float2 bv = *(const float2*)(bias + cb);
                float v0 = acc[mt][nt][0] + bv.x;
                float v1 = acc[mt][nt][1] + bv.y;
                float v2 = acc[mt][nt][2] + bv.x;
                float v3 = acc[mt][nt][3] + bv.y;
                if (EPI == EPI_GELU) {
                    v0 *= normcdff(v0); v1 *= normcdff(v1);
                    v2 *= normcdff(v2); v3 *= normcdff(v3);
                }
                __half2 h0 = __floats2half2_rn(v0, v1);
                __half2 h1 = __floats2half2_rn(v2, v3);
                *(__half2*)&hsm[row * 264 + col] = h0;
                *(__half2*)&hsm[(row + 8) * 264 + col] = h1;
            }
        }
        __syncthreads();
#pragma unroll
        for (int p = 0; p < 8; p++) {
            int idx = tid + p * 512;
            int row = idx >> 5, c16 = idx & 31;
            uint4 v = *(uint4*)&hsm[row * 264 + c16 * 8];
            *(uint4*)(Ch + (size_t)(m0 + row) * NTOT + n0 + c16 * 8) = v;
        }
        return;
    }

#pragma unroll
    for (int mt = 0; mt < 4; mt++) {
        int r0 = m0 + wm0 + mt * 16 + g;
#pragma unroll
        for (int nt = 0; nt < 4; nt++) {
            int cb = n0 + wn0 + nt * 8 + 2 * tq;
            float2 bv = *(const float2*)(bias + cb);
            float v0 = acc[mt][nt][0] + bv.x;
            float v1 = acc[mt][nt][1] + bv.y;
            float v2 = acc[mt][nt][2] + bv.x;
            float v3 = acc[mt][nt][3] + bv.y;
            if (EPI == EPI_GELU) {
                v0 *= normcdff(v0); v1 *= normcdff(v1);
                v2 *= normcdff(v2); v3 *= normcdff(v3);
            }
            size_t o0 = (size_t)r0 * NTOT + cb;
            size_t o1 = (size_t)(r0 + 8) * NTOT + cb;
            if (EPI == EPI_RES) {
                float2 r0v = *(const float2*)(res + o0);
                float2 r1v = *(const float2*)(res + o1);
                v0 += r0v.x; v1 += r0v.y; v2 += r1v.x; v3 += r1v.y;
            }
            if (WF32) {
                float2 s0 = {v0, v1}, s1 = {v2, v3};
                *(float2*)(C + o0) = s0;
                *(float2*)(C + o1) = s1;
            }
        }
    }
}

// ---------------- context partials via mma (cp.async 2-stage pipeline) ------
__global__ __launch_bounds__(256, 2)
void ctx_mma(const __half* __restrict__ qkvh, float* __restrict__ ctxp) {
    __shared__ __half Kt[2][32][136];
    __shared__ __half Vt[2][32][136];
    const int bh = blockIdx.x, split = blockIdx.y;
    const int b = bh >> 2, h = bh & 3;
    const int tid = threadIdx.x, lane = tid & 31, wid = tid >> 5;
    const int wm0 = (wid >> 2) * 64, wn0 = (wid & 3) * 32;
    const int g = lane >> 2, tq = lane & 3;
    const uint32_t kb0 = smem_u32(&Kt[0][0][0]);
    const uint32_t vb0 = smem_u32(&Vt[0][0][0]);
    const uint32_t STG = 32 * 136 * 2;              // stage stride (bytes)

    float acc[4][4][4];
#pragma unroll
    for (int i = 0; i < 4; i++)
#pragma unroll
        for (int j = 0; j < 4; j++)
#pragma unroll
            for (int c = 0; c < 4; c++) acc[i][j][c] = 0.f;

    const int arA = lane & 7, acA = (lane >> 3) & 1, asA = (lane >> 4) & 1;
    const int a_r = lane & 15, a_c = (lane >> 4) * 8;
    const int NCH = (NN / CSPLIT) / 32;             // 16 chunks
    const int n0base = split * (NN / CSPLIT);

    // per-thread load coords (2 x 16B for K, 2 for V)
    const int r0l = (tid) >> 4,        gc0 = (tid) & 15;
    const int r1l = (tid + 256) >> 4,  gc1 = (tid + 256) & 15;

    auto pf = [&](int ch, int st) {
        int nb = n0base + ch * 32;
        size_t s0 = ((size_t)(b * NN + nb + r0l)) * 1536 + (size_t)h * DD + gc0 * 8;
        size_t s1 = ((size_t)(b * NN + nb + r1l)) * 1536 + (size_t)h * DD + gc1 * 8;
        uint32_t o0 = (uint32_t)(r0l * 136 + gc0 * 8) * 2 + st * STG;
        uint32_t o1 = (uint32_t)(r1l * 136 + gc1 * 8) * 2 + st * STG;
        cpa16(kb0 + o0, qkvh + s0 + 512);
        cpa16(kb0 + o1, qkvh + s1 + 512);
        cpa16(vb0 + o0, qkvh + s0 + 1024);
        cpa16(vb0 + o1, qkvh + s1 + 1024);
        CP_COMMIT();
    };

    pf(0, 0);
#pragma unroll 1
    for (int ch = 0; ch < NCH; ch++) {
        const int st = ch & 1;
        CP_WAIT0();
        __syncthreads();                 // prior reads of stage st done + data visible
        if (ch + 1 < NCH) pf(ch + 1, st ^ 1);
        const uint32_t kb = kb0 + st * STG;
        const uint32_t vb = vb0 + st * STG;
#pragma unroll
        for (int ks = 0; ks < 2; ks++) {
            unsigned af[4][4], bf[4][2];
#pragma unroll
            for (int mt = 0; mt < 4; mt++)
                ldsm4t(af[mt][0], af[mt][1], af[mt][2], af[mt][3],
                       kb + (uint32_t)((ks * 16 + arA + asA * 8) * 136 +
                                       wm0 + mt * 16 + acA * 8) * 2);
#pragma unroll
            for (int nq = 0; nq < 2; nq++)
                ldsm4t(bf[2 * nq][0], bf[2 * nq][1], bf[2 * nq + 1][0], bf[2 * nq + 1][1],
                       vb + (uint32_t)((ks * 16 + a_r) * 136 + wn0 + nq * 16 + a_c) * 2);
#pragma unroll
            for (int mt = 0; mt < 4; mt++)
#pragma unroll
                for (int nt = 0; nt < 4; nt++)
                    mma_f16(acc[mt][nt], af[mt], bf[nt]);
        }
    }
    float* outp = ctxp + ((size_t)split * 16 + bh) * (DD * DD);
#pragma unroll
    for (int mt = 0; mt < 4; mt++) {
        int d = wm0 + mt * 16 + g;
#pragma unroll
        for (int nt = 0; nt < 4; nt++) {
            int e = wn0 + nt * 8 + 2 * tq;
            float2 s0 = {acc[mt][nt][0], acc[mt][nt][1]};
            float2 s1 = {acc[mt][nt][2], acc[mt][nt][3]};
            *(float2*)(outp + (size_t)d * DD + e) = s0;
            *(float2*)(outp + (size_t)(d + 8) * DD + e) = s1;
        }
    }
}

__global__ void reduce_ctx(const float* __restrict__ ctxp, __half* __restrict__ ctxh) {
    int i = blockIdx.x * blockDim.x + threadIdx.x;
    float s = 0.f;
#pragma unroll
    for (int sp = 0; sp < CSPLIT; sp++) s += ctxp[(size_t)sp * (16 * DD * DD) + i];
    ctxh[i] = __float2half(s * SCALE);
}

// ---------------- attn = q @ (ctx*scale) via mma, fp16 out ----------------
#define ASM_BYTES (2 * 128 * 136 * 2)
__global__ __launch_bounds__(256, 2)
void attn_mma(const __half* __restrict__ qkvh, const __half* __restrict__ ctxh,
              __half* __restrict__ attnh) {
    extern __shared__ __half asmem[];
    __half* Qs = asmem;
    __half* Cs = asmem + 128 * 136;
    const int tile = blockIdx.x, bh = blockIdx.y;
    const int b = bh >> 2, h = bh & 3;
    const int tid = threadIdx.x, lane = tid & 31, wid = tid >> 5;
    const int wm0 = (wid >> 2) * 64, wn0 = (wid & 3) * 32;
    const int g = lane >> 2, tq = lane & 3;

#pragma unroll
    for (int i = 0; i < 8; i++) {
        int idx = tid + i * 256;
        int row = idx >> 4, gc = idx & 15;
        *(uint4*)&Qs[row * 136 + gc * 8] =
            *(const uint4*)(qkvh + ((size_t)(b * NN + tile * 128 + row)) * 1536 +
                            (size_t)h * DD + gc * 8);
        *(uint4*)&Cs[row * 136 + gc * 8] =
            *(const uint4*)(ctxh + (size_t)bh * (DD * DD) + (size_t)row * DD + gc * 8);
    }
    __syncthreads();

    float acc[4][4][4];
#pragma unroll
    for (int i = 0; i < 4; i++)
#pragma unroll
        for (int j = 0; j < 4; j++)
#pragma unroll
            for (int c = 0; c < 4; c++) acc[i][j][c] = 0.f;

    const uint32_t qb = smem_u32(Qs), cb2 = smem_u32(Cs);
    const int a_r = lane & 15, a_c = (lane >> 4) * 8;

#pragma unroll
    for (int ks = 0; ks < 8; ks++) {
        unsigned af[4][4], bf[4][2];
#pragma unroll
        for (int mt = 0; mt < 4; mt++)
            ldsm4(af[mt][0], af[mt][1], af[mt][2], af[mt][3],
                  qb + (uint32_t)((wm0 + mt * 16 + a_r) * 136 + ks * 16 + a_c) * 2);
#pragma unroll
        for (int nq = 0; nq < 2; nq++)
            ldsm4t(bf[2 * nq][0], bf[2 * nq][1], bf[2 * nq + 1][0], bf[2 * nq + 1][1],
                   cb2 + (uint32_t)((ks * 16 + a_r) * 136 + wn0 + nq * 16 + a_c) * 2);
#pragma unroll
        for (int mt = 0; mt < 4; mt++)
#pragma unroll
            for (int nt = 0; nt < 4; nt++)
                mma_f16(acc[mt][nt], af[mt], bf[nt]);
    }

    // ---- smem-staged fp16 store (reuse Qs region) ----
    __syncthreads();
#pragma unroll
    for (int mt = 0; mt < 4; mt++) {
        int row = wm0 + mt * 16 + g;
#pragma unroll
        for (int nt = 0; nt < 4; nt++) {
            int col = wn0 + nt * 8 + 2 * tq;
            __half2 h0 = __floats2half2_rn(acc[mt][nt][0], acc[mt][nt][1]);
            __half2 h1 = __floats2half2_rn(acc[mt][nt][2], acc[mt][nt][3]);
            *(__half2*)&Qs[row * 136 + col] = h0;
            *(__half2*)&Qs[(row + 8) * 136 + col] = h1;
        }
    }
    __syncthreads();
#pragma unroll
    for (int p = 0; p < 8; p++) {
        int idx = tid + p * 256;
        int row = idx >> 4, c16 = idx & 15;
        uint4 v = *(uint4*)&Qs[row * 136 + c16 * 8];
        *(uint4*)(attnh + (size_t)(b * NN + tile * 128 + row) * CC + h * DD + c16 * 8) = v;
    }
}

// ---------------- launch ----------------
extern "C" void kernel_launch(void* const* d_in, const int* in_sizes, int n_in,
                              void* d_out, int out_size) {
    const float* x       = (const float*)d_in[0];
    const float* norm1_w = (const float*)d_in[1];
    const float* norm1_b = (const float*)d_in[2];
    const float* qkv_w   = (const float*)d_in[3];
    const float* qkv_b   = (const float*)d_in[4];
    const float* lnk_w   = (const float*)d_in[5];
    const float* lnk_b   = (const float*)d_in[6];
    const float* lnv_w   = (const float*)d_in[7];
    const float* lnv_b   = (const float*)d_in[8];
    const float* proj_w  = (const float*)d_in[9];
    const float* proj_b  = (const float*)d_in[10];
    const float* norm2_w = (const float*)d_in[11];
    const float* norm2_b = (const float*)d_in[12];
    const float* mlp_w1  = (const float*)d_in[13];
    const float* mlp_b1  = (const float*)d_in[14];
    const float* mlp_w2  = (const float*)d_in[15];
    const float* mlp_b2  = (const float*)d_in[16];
    float* out = (float*)d_out;

    float  *x1, *ctxp;
    __half *xh, *qkvh, *attnh, *mlphh, *ctxh, *wh;
    cudaGetSymbolAddress((void**)&x1,    g_x1);
    cudaGetSymbolAddress((void**)&ctxp,  g_ctxp);
    cudaGetSymbolAddress((void**)&xh,    g_xh);
    cudaGetSymbolAddress((void**)&qkvh,  g_qkvh);
    cudaGetSymbolAddress((void**)&attnh, g_attnh);
    cudaGetSymbolAddress((void**)&mlphh, g_mlphh);
    cudaGetSymbolAddress((void**)&ctxh,  g_ctxh);
    cudaGetSymbolAddress((void**)&wh,    g_wh);

    cudaFuncSetAttribute(qkv512,
                         cudaFuncAttributeMaxDynamicSharedMemorySize, HSM_BYTES);
    cudaFuncSetAttribute(hgemm512<512, 512, 1, 0, EPI_RES>,
                         cudaFuncAttributeMaxDynamicSharedMemorySize, HSM_BYTES);
    cudaFuncSetAttribute(hgemm512<2048, 512, 0, 1, EPI_GELU>,
                         cudaFuncAttributeMaxDynamicSharedMemorySize, HSM_BYTES);
    cudaFuncSetAttribute(hgemm512<512, 2048, 1, 0, EPI_RES>,
                         cudaFuncAttributeMaxDynamicSharedMemorySize, HSM_BYTES);
    cudaFuncSetAttribute(attn_mma,
                         cudaFuncAttributeMaxDynamicSharedMemorySize, ASM_BYTES);

    // 0. all weights -> fp16 (one launch)
    f2h_all<<<3072, 256>>>(qkv_w, proj_w, mlp_w1, mlp_w2, wh);

    // 1. LN1 -> fp16
    ln_rows512<<<MTOK, 256>>>(x, xh, norm1_w, norm1_b);
    // 2. qkv = xn @ qkv_w + b, fused k/v LN, fp16 out
    qkv512<<<dim3(6, 256), 512, HSM_BYTES>>>(
        xh, wh + WH_QKV, qkvh, qkv_b, lnk_w, lnk_b, lnv_w, lnv_b);
    // 3. context = k^T v ; reduce * SCALE -> fp16
    ctx_mma<<<dim3(16, CSPLIT), 256>>>(qkvh, ctxp);
    reduce_ctx<<<1024, 256>>>(ctxp, ctxh);
    // 4. attn = q @ ctx -> fp16
    attn_mma<<<dim3(64, 16), 256, ASM_BYTES>>>(qkvh, ctxh, attnh);
    // 5. x1 = x + attn @ proj_w + b  (fp32)
    hgemm512<512, 512, 1, 0, EPI_RES><<<dim3(2, 256), 512, HSM_BYTES>>>(
        attnh, wh + WH_PROJ, x1, nullptr, proj_b, x);
    // 6. LN2 -> fp16
    ln_rows512<<<MTOK, 256>>>(x1, xh, norm2_w, norm2_b);
    // 7. mlp hidden = gelu(h @ w1 + b1)  (fp16 only)
    hgemm512<2048, 512, 0, 1, EPI_GELU><<<dim3(8, 256), 512, HSM_BYTES>>>(
        xh, wh + WH_MLP1, nullptr, mlphh, mlp_b1, nullptr);
    // 8. out = x1 + mlph @ w2 + b2  (fp32)
    hgemm512<512, 2048, 1, 0, EPI_RES><<<dim3(2, 256), 512, HSM_BYTES>>>(
        mlphh, wh + WH_MLP2, out, nullptr, mlp_b2, x1);
}